// round 1
// baseline (speedup 1.0000x reference)
#include <cuda_runtime.h>
#include <math.h>

// Problem constants
#define B_   4
#define S_   1024
#define F_   256
#define H_   8
#define ROWS (B_ * S_)      // 4096
#define FH   (F_ * H_)      // 2048
#define BH   (B_ * H_)      // 32
#define SF   (S_ * F_)      // 262144 (per (b,h) Q/K/V/O block)
#define SS   (S_ * S_)      // 1048576 (per (b,h) score block)
#define SCALE 16.0f         // sqrt(256)

// Scratch (allocation-free: __device__ globals)
__device__ float g_Q[BH * SF];            // [b,h,s,f]  32 MB
__device__ float g_K[BH * SF];            // 32 MB
__device__ float g_V[BH * SF];            // 32 MB
__device__ float g_O[BH * SF];            // 32 MB
__device__ float g_S[(size_t)BH * SS];    // [b,h,i,j] 128 MB

// ---------------------------------------------------------------------------
// Kernel 1: QKV projection.  C[4096,2048] = A[4096,256] @ W[256,2048]
// blockIdx.z selects Wq/Wk/Wv and destination.  Store permuted into [b,h,s,f]:
//   row r -> b=r>>10, s=r&1023 ; col c -> h=c&7, f=c>>3
// ---------------------------------------------------------------------------
__global__ __launch_bounds__(256, 2)
void qkv_kernel(const float* __restrict__ A,
                const float* __restrict__ Wq,
                const float* __restrict__ Wk,
                const float* __restrict__ Wv)
{
    const float* W = (blockIdx.z == 0) ? Wq : (blockIdx.z == 1) ? Wk : Wv;
    float* Dst = (blockIdx.z == 0) ? g_Q : (blockIdx.z == 1) ? g_K : g_V;

    __shared__ float As[16][128];
    __shared__ float Bs[16][128];

    const int tid = threadIdx.x;
    const int tx = tid & 15;       // 0..15 -> col group
    const int ty = tid >> 4;       // 0..15 -> row group
    const int m0 = blockIdx.y * 128;
    const int n0 = blockIdx.x * 128;

    float acc[8][8];
#pragma unroll
    for (int i = 0; i < 8; i++)
#pragma unroll
        for (int j = 0; j < 8; j++) acc[i][j] = 0.f;

    for (int k0 = 0; k0 < F_; k0 += 16) {
        // Load A tile 128x16 (row-major, K=256), store transposed As[k][m]
        {
            const int r = tid >> 2;            // 0..63
            const int cv = (tid & 3) * 4;      // 0,4,8,12
#pragma unroll
            for (int rr = 0; rr < 128; rr += 64) {
                float4 a = *(const float4*)&A[(size_t)(m0 + r + rr) * F_ + k0 + cv];
                As[cv + 0][r + rr] = a.x;
                As[cv + 1][r + rr] = a.y;
                As[cv + 2][r + rr] = a.z;
                As[cv + 3][r + rr] = a.w;
            }
        }
        // Load W tile 16x128 (row-major, N=2048)
        {
            const int kr = tid >> 5;           // 0..7
            const int cv = (tid & 31) * 4;     // 0..124
#pragma unroll
            for (int kk = 0; kk < 16; kk += 8) {
                float4 b = *(const float4*)&W[(size_t)(k0 + kr + kk) * FH + n0 + cv];
                *(float4*)&Bs[kr + kk][cv] = b;
            }
        }
        __syncthreads();
#pragma unroll
        for (int k = 0; k < 16; k++) {
            float a[8], b[8];
            *(float4*)&a[0] = *(const float4*)&As[k][ty * 8];
            *(float4*)&a[4] = *(const float4*)&As[k][ty * 8 + 4];
            *(float4*)&b[0] = *(const float4*)&Bs[k][tx * 8];
            *(float4*)&b[4] = *(const float4*)&Bs[k][tx * 8 + 4];
#pragma unroll
            for (int i = 0; i < 8; i++)
#pragma unroll
                for (int j = 0; j < 8; j++) acc[i][j] += a[i] * b[j];
        }
        __syncthreads();
    }

    // Permuted store into [b,h,s,f]
#pragma unroll
    for (int i = 0; i < 8; i++) {
        const int r = m0 + ty * 8 + i;
        const int bb = r >> 10;
        const int s = r & 1023;
#pragma unroll
        for (int j = 0; j < 8; j++) {
            const int c = n0 + tx * 8 + j;
            const int h = c & 7;
            const int f = c >> 3;
            Dst[(size_t)(bb * H_ + h) * SF + s * F_ + f] = acc[i][j];
        }
    }
}

// ---------------------------------------------------------------------------
// Kernel 2: scores.  Per z=(b*8+h):  S[i,j] = sigmoid(16 * sum_f Q[i,f]K[j,f])
// NT GEMM: M=N=1024, K=256
// ---------------------------------------------------------------------------
__global__ __launch_bounds__(256, 2)
void scores_kernel()
{
    const int z = blockIdx.z;
    const float* __restrict__ Q = g_Q + (size_t)z * SF;
    const float* __restrict__ K = g_K + (size_t)z * SF;
    float* __restrict__ Sout = g_S + (size_t)z * SS;

    __shared__ float As[16][128];
    __shared__ float Bs[16][128];

    const int tid = threadIdx.x;
    const int tx = tid & 15;
    const int ty = tid >> 4;
    const int m0 = blockIdx.y * 128;
    const int n0 = blockIdx.x * 128;

    float acc[8][8];
#pragma unroll
    for (int i = 0; i < 8; i++)
#pragma unroll
        for (int j = 0; j < 8; j++) acc[i][j] = 0.f;

    for (int k0 = 0; k0 < F_; k0 += 16) {
        const int r = tid >> 2;
        const int cv = (tid & 3) * 4;
#pragma unroll
        for (int rr = 0; rr < 128; rr += 64) {
            float4 a = *(const float4*)&Q[(size_t)(m0 + r + rr) * F_ + k0 + cv];
            As[cv + 0][r + rr] = a.x;
            As[cv + 1][r + rr] = a.y;
            As[cv + 2][r + rr] = a.z;
            As[cv + 3][r + rr] = a.w;
            float4 b = *(const float4*)&K[(size_t)(n0 + r + rr) * F_ + k0 + cv];
            Bs[cv + 0][r + rr] = b.x;
            Bs[cv + 1][r + rr] = b.y;
            Bs[cv + 2][r + rr] = b.z;
            Bs[cv + 3][r + rr] = b.w;
        }
        __syncthreads();
#pragma unroll
        for (int k = 0; k < 16; k++) {
            float a[8], b[8];
            *(float4*)&a[0] = *(const float4*)&As[k][ty * 8];
            *(float4*)&a[4] = *(const float4*)&As[k][ty * 8 + 4];
            *(float4*)&b[0] = *(const float4*)&Bs[k][tx * 8];
            *(float4*)&b[4] = *(const float4*)&Bs[k][tx * 8 + 4];
#pragma unroll
            for (int i = 0; i < 8; i++)
#pragma unroll
                for (int j = 0; j < 8; j++) acc[i][j] += a[i] * b[j];
        }
        __syncthreads();
    }

    // sigmoid epilogue + float4 stores
#pragma unroll
    for (int i = 0; i < 8; i++) {
        const int r = m0 + ty * 8 + i;
#pragma unroll
        for (int jv = 0; jv < 8; jv += 4) {
            float4 v;
            v.x = 1.f / (1.f + __expf(-SCALE * acc[i][jv + 0]));
            v.y = 1.f / (1.f + __expf(-SCALE * acc[i][jv + 1]));
            v.z = 1.f / (1.f + __expf(-SCALE * acc[i][jv + 2]));
            v.w = 1.f / (1.f + __expf(-SCALE * acc[i][jv + 3]));
            *(float4*)&Sout[(size_t)r * S_ + n0 + tx * 8 + jv] = v;
        }
    }
}

// ---------------------------------------------------------------------------
// Kernel 3: O = S @ V.  Per z: M=1024, N=256, K=1024 (NN)
// ---------------------------------------------------------------------------
__global__ __launch_bounds__(256, 2)
void av_kernel()
{
    const int z = blockIdx.z;
    const float* __restrict__ Smat = g_S + (size_t)z * SS;
    const float* __restrict__ V = g_V + (size_t)z * SF;
    float* __restrict__ O = g_O + (size_t)z * SF;

    __shared__ float As[16][128];
    __shared__ float Bs[16][128];

    const int tid = threadIdx.x;
    const int tx = tid & 15;
    const int ty = tid >> 4;
    const int m0 = blockIdx.y * 128;
    const int n0 = blockIdx.x * 128;   // 0 or 128

    float acc[8][8];
#pragma unroll
    for (int i = 0; i < 8; i++)
#pragma unroll
        for (int j = 0; j < 8; j++) acc[i][j] = 0.f;

    for (int k0 = 0; k0 < S_; k0 += 16) {
        {
            const int r = tid >> 2;
            const int cv = (tid & 3) * 4;
#pragma unroll
            for (int rr = 0; rr < 128; rr += 64) {
                float4 a = *(const float4*)&Smat[(size_t)(m0 + r + rr) * S_ + k0 + cv];
                As[cv + 0][r + rr] = a.x;
                As[cv + 1][r + rr] = a.y;
                As[cv + 2][r + rr] = a.z;
                As[cv + 3][r + rr] = a.w;
            }
        }
        {
            const int kr = tid >> 5;
            const int cv = (tid & 31) * 4;
#pragma unroll
            for (int kk = 0; kk < 16; kk += 8) {
                float4 b = *(const float4*)&V[(size_t)(k0 + kr + kk) * F_ + n0 + cv];
                *(float4*)&Bs[kr + kk][cv] = b;
            }
        }
        __syncthreads();
#pragma unroll
        for (int k = 0; k < 16; k++) {
            float a[8], b[8];
            *(float4*)&a[0] = *(const float4*)&As[k][ty * 8];
            *(float4*)&a[4] = *(const float4*)&As[k][ty * 8 + 4];
            *(float4*)&b[0] = *(const float4*)&Bs[k][tx * 8];
            *(float4*)&b[4] = *(const float4*)&Bs[k][tx * 8 + 4];
#pragma unroll
            for (int i = 0; i < 8; i++)
#pragma unroll
                for (int j = 0; j < 8; j++) acc[i][j] += a[i] * b[j];
        }
        __syncthreads();
    }

#pragma unroll
    for (int i = 0; i < 8; i++) {
        const int r = m0 + ty * 8 + i;
#pragma unroll
        for (int jv = 0; jv < 8; jv += 4) {
            float4 v;
            v.x = acc[i][jv + 0];
            v.y = acc[i][jv + 1];
            v.z = acc[i][jv + 2];
            v.w = acc[i][jv + 3];
            *(float4*)&O[(size_t)r * F_ + n0 + tx * 8 + jv] = v;
        }
    }
}

// ---------------------------------------------------------------------------
// Kernel 4: out = relu( WV @ Wo ).  M=4096, N=256, K=2048.
// A is g_O gathered: A[r, kk] with kk = h*256 + f  ->  g_O[(b*8+h)*SF + s*256 + f]
// B is Wo gathered:  B[kk, n] = Wo[(f*8+h)*256 + n]
// 64x64 tiles, 4x4 microtiles, 256 threads.
// ---------------------------------------------------------------------------
__global__ __launch_bounds__(256, 2)
void out_kernel(const float* __restrict__ Wo, float* __restrict__ out)
{
    __shared__ float As[16][64];
    __shared__ float Bs[16][64];

    const int tid = threadIdx.x;
    const int tx = tid & 15;       // col group (0..15) -> 4 cols each
    const int ty = tid >> 4;       // row group (0..15) -> 4 rows each
    const int m0 = blockIdx.y * 64;
    const int n0 = blockIdx.x * 64;

    float acc[4][4];
#pragma unroll
    for (int i = 0; i < 4; i++)
#pragma unroll
        for (int j = 0; j < 4; j++) acc[i][j] = 0.f;

    for (int k0 = 0; k0 < FH; k0 += 16) {
        const int h = k0 >> 8;          // constant within this k-tile
        const int fbase = k0 & 255;
        // A tile: 64 rows x 16 k
        {
            const int r = tid >> 2;            // 0..63
            const int cv = (tid & 3) * 4;      // 0,4,8,12
            const int rg = m0 + r;
            const int bb = rg >> 10;
            const int s = rg & 1023;
            float4 a = *(const float4*)&g_O[(size_t)(bb * H_ + h) * SF + s * F_ + fbase + cv];
            As[cv + 0][r] = a.x;
            As[cv + 1][r] = a.y;
            As[cv + 2][r] = a.z;
            As[cv + 3][r] = a.w;
        }
        // B tile: 16 k x 64 n
        {
            const int kr = tid >> 4;           // 0..15
            const int cv = (tid & 15) * 4;     // 0..60
            float4 b = *(const float4*)&Wo[(size_t)((fbase + kr) * H_ + h) * F_ + n0 + cv];
            *(float4*)&Bs[kr][cv] = b;
        }
        __syncthreads();
#pragma unroll
        for (int k = 0; k < 16; k++) {
            float a[4], b[4];
            *(float4*)&a[0] = *(const float4*)&As[k][ty * 4];
            *(float4*)&b[0] = *(const float4*)&Bs[k][tx * 4];
#pragma unroll
            for (int i = 0; i < 4; i++)
#pragma unroll
                for (int j = 0; j < 4; j++) acc[i][j] += a[i] * b[j];
        }
        __syncthreads();
    }

#pragma unroll
    for (int i = 0; i < 4; i++) {
        const int r = m0 + ty * 4 + i;
        float4 v;
        v.x = fmaxf(acc[i][0], 0.f);
        v.y = fmaxf(acc[i][1], 0.f);
        v.z = fmaxf(acc[i][2], 0.f);
        v.w = fmaxf(acc[i][3], 0.f);
        *(float4*)&out[(size_t)r * F_ + n0 + tx * 4] = v;
    }
}

// ---------------------------------------------------------------------------
extern "C" void kernel_launch(void* const* d_in, const int* in_sizes, int n_in,
                              void* d_out, int out_size)
{
    const float* q_input = (const float*)d_in[0];
    const float* Wq = (const float*)d_in[1];
    const float* Wk = (const float*)d_in[2];
    const float* Wv = (const float*)d_in[3];
    const float* Wo = (const float*)d_in[4];
    float* out = (float*)d_out;

    // 1) QKV projections -> [b,h,s,f] scratch
    {
        dim3 grid(FH / 128, ROWS / 128, 3);   // (16, 32, 3)
        qkv_kernel<<<grid, 256>>>(q_input, Wq, Wk, Wv);
    }
    // 2) S = sigmoid(16 * Q K^T)
    {
        dim3 grid(S_ / 128, S_ / 128, BH);    // (8, 8, 32)
        scores_kernel<<<grid, 256>>>();
    }
    // 3) O = S V
    {
        dim3 grid(F_ / 128, S_ / 128, BH);    // (2, 8, 32)
        av_kernel<<<grid, 256>>>();
    }
    // 4) out = relu(O' Wo)
    {
        dim3 grid(F_ / 64, ROWS / 64);        // (4, 64)
        out_kernel<<<grid, 256>>>(Wo, out);
    }
}

// round 2
// speedup vs baseline: 2.6388x; 2.6388x over previous
#include <cuda_runtime.h>
#include <cstdint>
#include <math.h>

// Problem constants
#define B_   4
#define S_   1024
#define F_   256
#define H_   8
#define ROWS (B_ * S_)      // 4096
#define FH   (F_ * H_)      // 2048
#define BH   (B_ * H_)      // 32
#define SF   (S_ * F_)      // 262144 per (b,h)
#define SS   (S_ * S_)      // 1048576 per (b,h)
#define SCALE 16.0f

#define BM 128
#define BN 256
#define BK 16

// ---------------------------------------------------------------------------
// Scratch (__device__ globals; allocation-free)
// ---------------------------------------------------------------------------
__device__ float g_X[ROWS * F_];          // tf32-rounded q_input
__device__ float g_Wq[F_ * FH];           // tf32, columns permuted to h*256+f
__device__ float g_Wk[F_ * FH];
__device__ float g_Wv[F_ * FH];
__device__ float g_Wo[FH * F_];           // tf32, rows permuted to h*256+f
__device__ float g_Q[BH * SF];            // [b,h,s,f]
__device__ float g_K[BH * SF];
__device__ float g_V[BH * SF];
__device__ float g_O[BH * SF];
__device__ float g_S[(size_t)BH * SS];    // scores; later reused as split-K partials

// ---------------------------------------------------------------------------
// Helpers
// ---------------------------------------------------------------------------
__device__ __forceinline__ float tf32r(float x) {
    uint32_t u;
    asm("cvt.rna.tf32.f32 %0, %1;" : "=r"(u) : "f"(x));
    return __uint_as_float(u);
}

__device__ __forceinline__ int swz(int k) {            // bank swizzle, bits 3-4
    return (((k & 3) ^ ((k >> 2) & 3)) << 3);
}

__device__ __forceinline__ void mma_tf32(float d[4],
                                         const uint32_t a[4], const uint32_t b[2]) {
    asm volatile(
        "mma.sync.aligned.m16n8k8.row.col.f32.tf32.tf32.f32 "
        "{%0,%1,%2,%3},{%4,%5,%6,%7},{%8,%9},{%0,%1,%2,%3};\n"
        : "+f"(d[0]), "+f"(d[1]), "+f"(d[2]), "+f"(d[3])
        : "r"(a[0]), "r"(a[1]), "r"(a[2]), "r"(a[3]), "r"(b[0]), "r"(b[1]));
}

// A tile 128m x 16k from row-major src (src pre-offset to tile origin)
__device__ __forceinline__ void ldA(const float* src, int ld, int k0,
                                    float4 va[2], int tid) {
#pragma unroll
    for (int it = 0; it < 2; it++) {
        int idx = tid + it * 256;
        int m = idx >> 2, c = idx & 3;
        va[it] = *(const float4*)(src + (size_t)m * ld + k0 + 4 * c);
    }
}
__device__ __forceinline__ void stA(float* As, const float4 va[2], int tid) {
#pragma unroll
    for (int it = 0; it < 2; it++) {
        int idx = tid + it * 256;
        int m = idx >> 2, c = idx & 3;
        const float* f = (const float*)&va[it];
#pragma unroll
        for (int i = 0; i < 4; i++) {
            int k = 4 * c + i;
            As[k * BM + (m ^ swz(k))] = f[i];
        }
    }
}

// B tile 16k x 256n from row-major [K][N] src (pre-offset by n0)
__device__ __forceinline__ void ldB(const float* src, int ld, int k0,
                                    float4 vb[4], int tid) {
#pragma unroll
    for (int it = 0; it < 4; it++) {
        int idx = tid + it * 256;
        int k = idx >> 6, nv = (idx & 63) * 4;
        vb[it] = *(const float4*)(src + (size_t)(k0 + k) * ld + nv);
    }
}
__device__ __forceinline__ void stB(float* Bs, const float4 vb[4], int tid) {
#pragma unroll
    for (int it = 0; it < 4; it++) {
        int idx = tid + it * 256;
        int k = idx >> 6, nv = (idx & 63) * 4;
        *(float4*)&Bs[k * BN + (nv ^ swz(k))] = vb[it];
    }
}

// B tile via transpose from row-major [N][K] src (scores: K-matrix), pre-offset n0
__device__ __forceinline__ void ldBT(const float* src, int ld, int k0,
                                     float4 vb[4], int tid) {
#pragma unroll
    for (int it = 0; it < 4; it++) {
        int idx = tid + it * 256;
        int n = idx >> 2, c = idx & 3;
        vb[it] = *(const float4*)(src + (size_t)n * ld + k0 + 4 * c);
    }
}
__device__ __forceinline__ void stBT(float* Bs, const float4 vb[4], int tid) {
#pragma unroll
    for (int it = 0; it < 4; it++) {
        int idx = tid + it * 256;
        int n = idx >> 2, c = idx & 3;
        const float* f = (const float*)&vb[it];
#pragma unroll
        for (int i = 0; i < 4; i++) {
            int k = 4 * c + i;
            Bs[k * BN + (n ^ swz(k))] = f[i];
        }
    }
}

// One BK=16 slice of warp-level mma: 64x64 warp tile
__device__ __forceinline__ void mma_slice(const float* As, const float* Bs,
                                          int wm, int wn, int lane,
                                          float acc[4][8][4]) {
    const int g = lane >> 2, t = lane & 3;
    const uint32_t* uA = (const uint32_t*)As;
    const uint32_t* uB = (const uint32_t*)Bs;
#pragma unroll
    for (int kk = 0; kk < BK; kk += 8) {
        const int k0 = kk + t, k1 = kk + t + 4;
        const int s0 = swz(k0), s1 = swz(k1);
        const uint32_t* A0 = uA + k0 * BM;
        const uint32_t* A1 = uA + k1 * BM;
        const uint32_t* B0 = uB + k0 * BN;
        const uint32_t* B1 = uB + k1 * BN;
        uint32_t a[4][4], b[8][2];
#pragma unroll
        for (int mt = 0; mt < 4; mt++) {
            int m = wm + 16 * mt + g;
            a[mt][0] = A0[m ^ s0];
            a[mt][1] = A0[(m + 8) ^ s0];
            a[mt][2] = A1[m ^ s1];
            a[mt][3] = A1[(m + 8) ^ s1];
        }
#pragma unroll
        for (int nt = 0; nt < 8; nt++) {
            int n = wn + 8 * nt + g;
            b[nt][0] = B0[n ^ s0];
            b[nt][1] = B1[n ^ s1];
        }
#pragma unroll
        for (int mt = 0; mt < 4; mt++)
#pragma unroll
            for (int nt = 0; nt < 8; nt++)
                mma_tf32(acc[mt][nt], a[mt], b[nt]);
    }
}

#define GEMM_PROLOGUE()                                                        \
    __shared__ float As[2][BK * BM];                                           \
    __shared__ float Bs[2][BK * BN];                                           \
    const int tid = threadIdx.x;                                               \
    const int lane = tid & 31;                                                 \
    const int w = tid >> 5;                                                    \
    const int wm = (w & 1) * 64;                                               \
    const int wn = (w >> 1) * 64;                                              \
    const int g = lane >> 2, t = lane & 3;                                     \
    float acc[4][8][4];                                                        \
    _Pragma("unroll") for (int i = 0; i < 4; i++)                              \
        _Pragma("unroll") for (int j = 0; j < 8; j++)                          \
            _Pragma("unroll") for (int q = 0; q < 4; q++) acc[i][j][q] = 0.f;

// ---------------------------------------------------------------------------
// Prep: tf32-round inputs; permute W columns (f*8+h -> h*256+f) and Wo rows
// ---------------------------------------------------------------------------
__global__ void prep_kernel(const float* __restrict__ X,
                            const float* __restrict__ Wq,
                            const float* __restrict__ Wk,
                            const float* __restrict__ Wv,
                            const float* __restrict__ Wo) {
    const int i = blockIdx.x * 256 + threadIdx.x;
    const int z = blockIdx.y;
    if (z == 0) {
        if (i < ROWS * F_) g_X[i] = tf32r(X[i]);
    } else if (z <= 3) {
        if (i < F_ * FH) {
            int k = i >> 11, c = i & 2047;
            int h = c >> 8, f = c & 255;
            float v = (z == 1 ? Wq : z == 2 ? Wk : Wv)[k * FH + f * 8 + h];
            (z == 1 ? g_Wq : z == 2 ? g_Wk : g_Wv)[i] = tf32r(v);
        }
    } else {
        if (i < FH * F_) {
            int kk = i >> 8, n = i & 255;
            int h = kk >> 8, f = kk & 255;
            g_Wo[i] = tf32r(Wo[(f * 8 + h) * F_ + n]);
        }
    }
}

// ---------------------------------------------------------------------------
// QKV: C[4096, h*256+f] = X @ gW ; store to g_{Q,K,V}[b,h,s,f]
// grid (8, 32, 3)
// ---------------------------------------------------------------------------
__global__ __launch_bounds__(256, 1)
void qkv_kernel() {
    GEMM_PROLOGUE();
    const int m0 = blockIdx.y * BM;
    const int n0 = blockIdx.x * BN;       // = h * 256
    const int z = blockIdx.z;
    const float* srcA = g_X + (size_t)m0 * F_;
    const float* srcB = (z == 0 ? g_Wq : z == 1 ? g_Wk : g_Wv) + n0;
    float* dst = (z == 0 ? g_Q : z == 1 ? g_K : g_V);
    const int h = n0 >> 8;

    float4 va[2], vb[4];
    ldA(srcA, F_, 0, va, tid); ldB(srcB, FH, 0, vb, tid);
    stA(As[0], va, tid); stB(Bs[0], vb, tid);
    __syncthreads();
    int buf = 0;
    const int NS = F_ / BK;     // 16
#pragma unroll 1
    for (int s = 0; s < NS; s++) {
        if (s + 1 < NS) { ldA(srcA, F_, (s + 1) * BK, va, tid); ldB(srcB, FH, (s + 1) * BK, vb, tid); }
        mma_slice(As[buf], Bs[buf], wm, wn, lane, acc);
        if (s + 1 < NS) { stA(As[buf ^ 1], va, tid); stB(Bs[buf ^ 1], vb, tid); __syncthreads(); buf ^= 1; }
    }
#pragma unroll
    for (int mt = 0; mt < 4; mt++) {
        const int r0 = m0 + wm + 16 * mt + g;
#pragma unroll
        for (int nt = 0; nt < 8; nt++) {
            const int f = wn + 8 * nt + 2 * t;     // local col = feature
            const int b0r = r0 >> 10, s0r = r0 & 1023;
            const int r1 = r0 + 8;
            const int b1r = r1 >> 10, s1r = r1 & 1023;
            float2 v0 = { tf32r(acc[mt][nt][0]), tf32r(acc[mt][nt][1]) };
            float2 v1 = { tf32r(acc[mt][nt][2]), tf32r(acc[mt][nt][3]) };
            *(float2*)&dst[(size_t)(b0r * H_ + h) * SF + s0r * F_ + f] = v0;
            *(float2*)&dst[(size_t)(b1r * H_ + h) * SF + s1r * F_ + f] = v1;
        }
    }
}

// ---------------------------------------------------------------------------
// Scores: per z, S = sigmoid(16 * Q K^T).  grid (4, 8, 32)
// ---------------------------------------------------------------------------
__global__ __launch_bounds__(256, 1)
void scores_kernel() {
    GEMM_PROLOGUE();
    const int m0 = blockIdx.y * BM;
    const int n0 = blockIdx.x * BN;
    const int z = blockIdx.z;
    const float* srcA = g_Q + (size_t)z * SF + (size_t)m0 * F_;
    const float* srcB = g_K + (size_t)z * SF + (size_t)n0 * F_;
    float* Sout = g_S + (size_t)z * SS;

    float4 va[2], vb[4];
    ldA(srcA, F_, 0, va, tid); ldBT(srcB, F_, 0, vb, tid);
    stA(As[0], va, tid); stBT(Bs[0], vb, tid);
    __syncthreads();
    int buf = 0;
    const int NS = F_ / BK;
#pragma unroll 1
    for (int s = 0; s < NS; s++) {
        if (s + 1 < NS) { ldA(srcA, F_, (s + 1) * BK, va, tid); ldBT(srcB, F_, (s + 1) * BK, vb, tid); }
        mma_slice(As[buf], Bs[buf], wm, wn, lane, acc);
        if (s + 1 < NS) { stA(As[buf ^ 1], va, tid); stBT(Bs[buf ^ 1], vb, tid); __syncthreads(); buf ^= 1; }
    }
#pragma unroll
    for (int mt = 0; mt < 4; mt++) {
        const int r0 = m0 + wm + 16 * mt + g;
#pragma unroll
        for (int nt = 0; nt < 8; nt++) {
            const int c = n0 + wn + 8 * nt + 2 * t;
            float2 v0, v1;
            v0.x = tf32r(1.f / (1.f + __expf(-SCALE * acc[mt][nt][0])));
            v0.y = tf32r(1.f / (1.f + __expf(-SCALE * acc[mt][nt][1])));
            v1.x = tf32r(1.f / (1.f + __expf(-SCALE * acc[mt][nt][2])));
            v1.y = tf32r(1.f / (1.f + __expf(-SCALE * acc[mt][nt][3])));
            *(float2*)&Sout[(size_t)r0 * S_ + c] = v0;
            *(float2*)&Sout[(size_t)(r0 + 8) * S_ + c] = v1;
        }
    }
}

// ---------------------------------------------------------------------------
// AV: per z, O = S @ V.  grid (1, 8, 32)
// ---------------------------------------------------------------------------
__global__ __launch_bounds__(256, 1)
void av_kernel() {
    GEMM_PROLOGUE();
    const int m0 = blockIdx.y * BM;
    const int z = blockIdx.z;
    const float* srcA = g_S + (size_t)z * SS + (size_t)m0 * S_;
    const float* srcB = g_V + (size_t)z * SF;
    float* O = g_O + (size_t)z * SF;

    float4 va[2], vb[4];
    ldA(srcA, S_, 0, va, tid); ldB(srcB, F_, 0, vb, tid);
    stA(As[0], va, tid); stB(Bs[0], vb, tid);
    __syncthreads();
    int buf = 0;
    const int NS = S_ / BK;     // 64
#pragma unroll 1
    for (int s = 0; s < NS; s++) {
        if (s + 1 < NS) { ldA(srcA, S_, (s + 1) * BK, va, tid); ldB(srcB, F_, (s + 1) * BK, vb, tid); }
        mma_slice(As[buf], Bs[buf], wm, wn, lane, acc);
        if (s + 1 < NS) { stA(As[buf ^ 1], va, tid); stB(Bs[buf ^ 1], vb, tid); __syncthreads(); buf ^= 1; }
    }
#pragma unroll
    for (int mt = 0; mt < 4; mt++) {
        const int r0 = m0 + wm + 16 * mt + g;
#pragma unroll
        for (int nt = 0; nt < 8; nt++) {
            const int c = wn + 8 * nt + 2 * t;
            float2 v0 = { tf32r(acc[mt][nt][0]), tf32r(acc[mt][nt][1]) };
            float2 v1 = { tf32r(acc[mt][nt][2]), tf32r(acc[mt][nt][3]) };
            *(float2*)&O[(size_t)r0 * F_ + c] = v0;
            *(float2*)&O[(size_t)(r0 + 8) * F_ + c] = v1;
        }
    }
}

// ---------------------------------------------------------------------------
// OUT (split-K=4): partial[z] = O' @ gWo over k in [z*512,(z+1)*512)
// A[r][k] with k = h*256+f -> g_O[(b*8+h)*SF + s*256 + f].  grid (1, 32, 4)
// Partials stored in g_S (free after av_kernel).
// ---------------------------------------------------------------------------
__global__ __launch_bounds__(256, 1)
void out_kernel() {
    GEMM_PROLOGUE();
    const int m0 = blockIdx.y * BM;
    const int kbase = blockIdx.z * (FH / 4);   // 512-chunk
    float* P = g_S + (size_t)blockIdx.z * (ROWS * F_);

    float4 va[2], vb[4];
    const int NS = (FH / 4) / BK;              // 32

    auto ldAout = [&](int ks, float4 v[2]) {
        const int kg = kbase + ks;
        const int h = kg >> 8, f0 = kg & 255;
#pragma unroll
        for (int it = 0; it < 2; it++) {
            int idx = tid + it * 256;
            int m = idx >> 2, c = idx & 3;
            int r = m0 + m, b = r >> 10, srow = r & 1023;
            v[it] = *(const float4*)(g_O + (size_t)(b * H_ + h) * SF + srow * F_ + f0 + 4 * c);
        }
    };

    ldAout(0, va); ldB(g_Wo, F_, kbase, vb, tid);
    stA(As[0], va, tid); stB(Bs[0], vb, tid);
    __syncthreads();
    int buf = 0;
#pragma unroll 1
    for (int s = 0; s < NS; s++) {
        if (s + 1 < NS) { ldAout((s + 1) * BK, va); ldB(g_Wo, F_, kbase + (s + 1) * BK, vb, tid); }
        mma_slice(As[buf], Bs[buf], wm, wn, lane, acc);
        if (s + 1 < NS) { stA(As[buf ^ 1], va, tid); stB(Bs[buf ^ 1], vb, tid); __syncthreads(); buf ^= 1; }
    }
#pragma unroll
    for (int mt = 0; mt < 4; mt++) {
        const int r0 = m0 + wm + 16 * mt + g;
#pragma unroll
        for (int nt = 0; nt < 8; nt++) {
            const int c = wn + 8 * nt + 2 * t;
            float2 v0 = { acc[mt][nt][0], acc[mt][nt][1] };
            float2 v1 = { acc[mt][nt][2], acc[mt][nt][3] };
            *(float2*)&P[(size_t)r0 * F_ + c] = v0;
            *(float2*)&P[(size_t)(r0 + 8) * F_ + c] = v1;
        }
    }
}

__global__ void reduce_relu_kernel(float* __restrict__ out) {
    const int i = blockIdx.x * 256 + threadIdx.x;
    if (i < ROWS * F_) {
        float s = g_S[i] + g_S[(size_t)ROWS * F_ + i] +
                  g_S[2 * (size_t)ROWS * F_ + i] + g_S[3 * (size_t)ROWS * F_ + i];
        out[i] = fmaxf(s, 0.f);
    }
}

// ---------------------------------------------------------------------------
extern "C" void kernel_launch(void* const* d_in, const int* in_sizes, int n_in,
                              void* d_out, int out_size) {
    const float* q_input = (const float*)d_in[0];
    const float* Wq = (const float*)d_in[1];
    const float* Wk = (const float*)d_in[2];
    const float* Wv = (const float*)d_in[3];
    const float* Wo = (const float*)d_in[4];
    float* out = (float*)d_out;

    { dim3 grid(4096, 5); prep_kernel<<<grid, 256>>>(q_input, Wq, Wk, Wv, Wo); }
    { dim3 grid(FH / BN, ROWS / BM, 3); qkv_kernel<<<grid, 256>>>(); }        // (8,32,3)
    { dim3 grid(S_ / BN, S_ / BM, BH); scores_kernel<<<grid, 256>>>(); }      // (4,8,32)
    { dim3 grid(1, S_ / BM, BH); av_kernel<<<grid, 256>>>(); }                // (1,8,32)
    { dim3 grid(1, ROWS / BM, 4); out_kernel<<<grid, 256>>>(); }              // (1,32,4)
    { reduce_relu_kernel<<<(ROWS * F_ + 255) / 256, 256>>>(out); }
}

// round 6
// speedup vs baseline: 5.9000x; 2.2359x over previous
#include <cuda_runtime.h>
#include <cuda_fp16.h>
#include <cstdint>
#include <math.h>

// ---------------------------------------------------------------------------
// Problem constants
// ---------------------------------------------------------------------------
#define B_   4
#define S_   1024
#define F_   256
#define H_   8
#define ROWS 4096
#define FH   2048
#define BH   32
#define SF   262144            // S_*F_ per (b,h)
#define SS   1048576           // S_*S_ per (b,h)
#define SCALE 16.0f

#define BK   64                // k elems per smem stage (128 bytes fp16)
#define TM   128               // CTA tile M
#define TN   128               // CTA tile N
#define STAGE_BYTES 16384      // 128 rows * 128 B
#define BUF_BYTES   32768      // A stage + B stage
#define SMEM_TOTAL  65536      // double buffered

// ---------------------------------------------------------------------------
// Scratch (__device__ globals; allocation-free)
// ---------------------------------------------------------------------------
__device__ __half g_X[ROWS * F_];
__device__ __half g_Wqt[FH * F_];       // [n=h*256+f][k]
__device__ __half g_Wkt[FH * F_];
__device__ __half g_Wvt[FH * F_];
__device__ __half g_Wot[F_ * FH];       // [n][kk=h*256+f]
__device__ __half g_Q[BH * SF];         // [b,h][s][f]
__device__ __half g_K[BH * SF];
__device__ __half g_V[BH * SF];
__device__ __half g_Vt[BH * SF];        // [b,h][f][s]
__device__ __half g_O[BH * SF];
__device__ __half g_S[(size_t)BH * SS]; // [b,h][i][j]
__device__ float  g_P[4][ROWS * F_];    // split-K partials

// ---------------------------------------------------------------------------
// PTX helpers
// ---------------------------------------------------------------------------
__device__ __forceinline__ uint32_t smem_u32(const void* p) {
    uint32_t a;
    asm("{ .reg .u64 t; cvta.to.shared.u64 t, %1; cvt.u32.u64 %0, t; }"
        : "=r"(a) : "l"(p));
    return a;
}

__device__ __forceinline__ void cp16(uint32_t dst, const void* src) {
    asm volatile("cp.async.cg.shared.global [%0], [%1], 16;\n"
                 :: "r"(dst), "l"(src));
}
#define CP_COMMIT() asm volatile("cp.async.commit_group;\n" ::: "memory")
#define CP_WAIT0()  asm volatile("cp.async.wait_group 0;\n" ::: "memory")

__device__ __forceinline__ void mma16816(float d[4], const uint32_t a[4],
                                         const uint32_t b[2]) {
    asm volatile(
        "mma.sync.aligned.m16n8k16.row.col.f32.f16.f16.f32 "
        "{%0,%1,%2,%3},{%4,%5,%6,%7},{%8,%9},{%0,%1,%2,%3};\n"
        : "+f"(d[0]), "+f"(d[1]), "+f"(d[2]), "+f"(d[3])
        : "r"(a[0]), "r"(a[1]), "r"(a[2]), "r"(a[3]), "r"(b[0]), "r"(b[1]));
}

// ---------------------------------------------------------------------------
// Tile fill: 128 rows x 64 fp16 (128B rows), chunk swizzle c ^ (row&7).
// p(row, kElem) -> const __half* (16B aligned)
// ---------------------------------------------------------------------------
template <class P>
__device__ __forceinline__ void issue_tile(uint32_t sbase, P p, int k0, int tid) {
#pragma unroll
    for (int it = 0; it < 4; it++) {
        int idx = tid + it * 256;
        int row = idx >> 3, c = idx & 7;
        uint32_t dst = sbase + row * 128 + ((c ^ (row & 7)) << 4);
        cp16(dst, p(row, k0 + c * 8));
    }
}

// One BK=64 stage of mma: warp tile 64m x 32n, direct 4B LDS fragments
__device__ __forceinline__ void mma_stage(const char* As, const char* Bs,
                                          int wm, int wn, int g, int t,
                                          float acc[4][4][4]) {
#pragma unroll
    for (int kk = 0; kk < BK; kk += 16) {
        const int ch = kk >> 3;
        uint32_t a[4][4], b[4][2];
#pragma unroll
        for (int mt = 0; mt < 4; mt++) {
            int r0 = wm + mt * 16 + g, r1 = r0 + 8;
            const char* p0 = As + r0 * 128; int s0 = r0 & 7;
            const char* p1 = As + r1 * 128; int s1 = r1 & 7;
            a[mt][0] = *(const uint32_t*)(p0 + ((ch ^ s0) << 4) + 4 * t);
            a[mt][1] = *(const uint32_t*)(p1 + ((ch ^ s1) << 4) + 4 * t);
            a[mt][2] = *(const uint32_t*)(p0 + (((ch + 1) ^ s0) << 4) + 4 * t);
            a[mt][3] = *(const uint32_t*)(p1 + (((ch + 1) ^ s1) << 4) + 4 * t);
        }
#pragma unroll
        for (int nt = 0; nt < 4; nt++) {
            int r = wn + nt * 8 + g;
            const char* p = Bs + r * 128; int s = r & 7;
            b[nt][0] = *(const uint32_t*)(p + ((ch ^ s) << 4) + 4 * t);
            b[nt][1] = *(const uint32_t*)(p + (((ch + 1) ^ s) << 4) + 4 * t);
        }
#pragma unroll
        for (int mt = 0; mt < 4; mt++)
#pragma unroll
            for (int nt = 0; nt < 4; nt++)
                mma16816(acc[mt][nt], a[mt], b[nt]);
    }
}

// Mainloop driver: NS stages, double-buffered cp.async
template <int NS, class PA, class PB>
__device__ __forceinline__ void run_gemm(char* sm, PA pa, PB pb,
                                         float acc[4][4][4]) {
    const int tid = threadIdx.x;
    const int w = tid >> 5, lane = tid & 31;
    const int g = lane >> 2, t = lane & 3;
    const int wm = (w & 1) * 64, wn = (w >> 1) * 32;
    const uint32_t su = smem_u32(sm);

#pragma unroll
    for (int i = 0; i < 4; i++)
#pragma unroll
        for (int j = 0; j < 4; j++)
#pragma unroll
            for (int q = 0; q < 4; q++) acc[i][j][q] = 0.f;

    issue_tile(su, pa, 0, tid);
    issue_tile(su + STAGE_BYTES, pb, 0, tid);
    CP_COMMIT();

#pragma unroll 1
    for (int s = 0; s < NS; s++) {
        const int buf = s & 1;
        CP_WAIT0();
        __syncthreads();
        if (s + 1 < NS) {
            const int nb = buf ^ 1;
            issue_tile(su + nb * BUF_BYTES, pa, (s + 1) * BK, tid);
            issue_tile(su + nb * BUF_BYTES + STAGE_BYTES, pb, (s + 1) * BK, tid);
            CP_COMMIT();
        }
        mma_stage(sm + buf * BUF_BYTES, sm + buf * BUF_BYTES + STAGE_BYTES,
                  wm, wn, g, t, acc);
    }
}

// Epilogue vars: thread (g,t) of warp w; element (mt,nt): rows m0+wm+16mt+g(+8),
// cols n0+wn+8nt+2t(+1)
#define EPI_VARS()                               \
    const int tid = threadIdx.x;                 \
    const int w = tid >> 5, lane = tid & 31;     \
    const int g = lane >> 2, t = lane & 3;       \
    const int wm = (w & 1) * 64, wn = (w >> 1) * 32;

// ---------------------------------------------------------------------------
// Prep kernels
// ---------------------------------------------------------------------------
__global__ void prep_x(const float* __restrict__ X) {
    int i = blockIdx.x * 256 + threadIdx.x;
    g_X[i] = __float2half_rn(X[i]);
}

// W [k=256][c=f*8+h] -> Wt [n=h*256+f][k]
__global__ void prep_wqkv(const float* __restrict__ Wq,
                          const float* __restrict__ Wk,
                          const float* __restrict__ Wv) {
    __shared__ float T[32][33];
    const int z = blockIdx.z;
    const float* src = (z == 0) ? Wq : (z == 1) ? Wk : Wv;
    __half* dst = (z == 0) ? g_Wqt : (z == 1) ? g_Wkt : g_Wvt;
    const int c0 = blockIdx.x * 32, k0 = blockIdx.y * 32;
    const int tx = threadIdx.x, ty = threadIdx.y;
#pragma unroll
    for (int i = 0; i < 4; i++)
        T[ty + 8 * i][tx] = src[(size_t)(k0 + ty + 8 * i) * FH + c0 + tx];
    __syncthreads();
#pragma unroll
    for (int i = 0; i < 4; i++) {
        int c = c0 + ty + 8 * i;
        int n = (c & 7) * 256 + (c >> 3);
        dst[(size_t)n * F_ + k0 + tx] = __float2half_rn(T[tx][ty + 8 * i]);
    }
}

// Wo [row=f*8+h][n] -> Wot [n][kk=h*256+f]
__global__ void prep_wo(const float* __restrict__ Wo) {
    const int row = blockIdx.x;
    const int nn = threadIdx.x;
    int kk = ((row & 7) << 8) | (row >> 3);
    g_Wot[(size_t)nn * FH + kk] = __float2half_rn(Wo[(size_t)row * F_ + nn]);
}

// g_V [z][s][f] -> g_Vt [z][f][s]
__global__ void transpose_v() {
    __shared__ __half T[32][36];
    const size_t zoff = (size_t)blockIdx.z * SF;
    const int s0 = blockIdx.x * 32, f0 = blockIdx.y * 32;
    const int tx = threadIdx.x, ty = threadIdx.y;
#pragma unroll
    for (int i = 0; i < 4; i++)
        T[ty + 8 * i][tx] = g_V[zoff + (size_t)(s0 + ty + 8 * i) * F_ + f0 + tx];
    __syncthreads();
#pragma unroll
    for (int i = 0; i < 4; i++)
        g_Vt[zoff + (size_t)(f0 + ty + 8 * i) * S_ + s0 + tx] = T[tx][ty + 8 * i];
}

// ---------------------------------------------------------------------------
// GEMM kernels
// ---------------------------------------------------------------------------
// QKV: C[4096, 2048], A=g_X, B=Wt.  grid (16 n, 32 m, 3 z)
__global__ __launch_bounds__(256, 2)
void qkv_kernel() {
    extern __shared__ char sm[];
    const int m0 = blockIdx.y * TM;
    const int n0 = blockIdx.x * TN;
    const int z = blockIdx.z;
    const __half* Wt = (z == 0) ? g_Wqt : (z == 1) ? g_Wkt : g_Wvt;
    __half* dst = (z == 0) ? g_Q : (z == 1) ? g_K : g_V;
    const int h = n0 >> 8, f0 = n0 & 255;

    float acc[4][4][4];
    run_gemm<F_ / BK>(sm,
        [&](int r, int k) { return g_X + (size_t)(m0 + r) * F_ + k; },
        [&](int r, int k) { return Wt + (size_t)(n0 + r) * F_ + k; },
        acc);

    EPI_VARS();
#pragma unroll
    for (int mt = 0; mt < 4; mt++) {
        int r0 = m0 + wm + 16 * mt + g;
        __half* b0 = dst + (size_t)((r0 >> 10) * H_ + h) * SF + (r0 & 1023) * F_;
        __half* b1 = dst + (size_t)(((r0 + 8) >> 10) * H_ + h) * SF + ((r0 + 8) & 1023) * F_;
#pragma unroll
        for (int nt = 0; nt < 4; nt++) {
            int col = f0 + wn + nt * 8 + 2 * t;
            *(__half2*)(b0 + col) = __floats2half2_rn(acc[mt][nt][0], acc[mt][nt][1]);
            *(__half2*)(b1 + col) = __floats2half2_rn(acc[mt][nt][2], acc[mt][nt][3]);
        }
    }
}

// Scores: per z, S = sigmoid(16 * Q K^T).  grid (8 n, 8 m, 32 z)
__global__ __launch_bounds__(256, 2)
void scores_kernel() {
    extern __shared__ char sm[];
    const int m0 = blockIdx.y * TM;
    const int n0 = blockIdx.x * TN;
    const int z = blockIdx.z;
    const __half* Q = g_Q + (size_t)z * SF;
    const __half* Kp = g_K + (size_t)z * SF;
    __half* Sout = g_S + (size_t)z * SS;

    float acc[4][4][4];
    run_gemm<F_ / BK>(sm,
        [&](int r, int k) { return Q + (size_t)(m0 + r) * F_ + k; },
        [&](int r, int k) { return Kp + (size_t)(n0 + r) * F_ + k; },
        acc);

    EPI_VARS();
#pragma unroll
    for (int mt = 0; mt < 4; mt++) {
        int r0 = m0 + wm + 16 * mt + g;
#pragma unroll
        for (int nt = 0; nt < 4; nt++) {
            int col = n0 + wn + nt * 8 + 2 * t;
            float s0 = 1.f / (1.f + __expf(-SCALE * acc[mt][nt][0]));
            float s1 = 1.f / (1.f + __expf(-SCALE * acc[mt][nt][1]));
            float s2 = 1.f / (1.f + __expf(-SCALE * acc[mt][nt][2]));
            float s3 = 1.f / (1.f + __expf(-SCALE * acc[mt][nt][3]));
            *(__half2*)(Sout + (size_t)r0 * S_ + col) = __floats2half2_rn(s0, s1);
            *(__half2*)(Sout + (size_t)(r0 + 8) * S_ + col) = __floats2half2_rn(s2, s3);
        }
    }
}

// AV: per z, O = S @ V (B = Vt[f][s]).  grid (2 n, 8 m, 32 z)
__global__ __launch_bounds__(256, 2)
void av_kernel() {
    extern __shared__ char sm[];
    const int m0 = blockIdx.y * TM;
    const int n0 = blockIdx.x * TN;
    const int z = blockIdx.z;
    const __half* Sm = g_S + (size_t)z * SS;
    const __half* Vt = g_Vt + (size_t)z * SF;
    __half* O = g_O + (size_t)z * SF;

    float acc[4][4][4];
    run_gemm<S_ / BK>(sm,
        [&](int r, int k) { return Sm + (size_t)(m0 + r) * S_ + k; },
        [&](int r, int k) { return Vt + (size_t)(n0 + r) * S_ + k; },
        acc);

    EPI_VARS();
#pragma unroll
    for (int mt = 0; mt < 4; mt++) {
        int r0 = m0 + wm + 16 * mt + g;
#pragma unroll
        for (int nt = 0; nt < 4; nt++) {
            int col = n0 + wn + nt * 8 + 2 * t;
            *(__half2*)(O + (size_t)r0 * F_ + col) =
                __floats2half2_rn(acc[mt][nt][0], acc[mt][nt][1]);
            *(__half2*)(O + (size_t)(r0 + 8) * F_ + col) =
                __floats2half2_rn(acc[mt][nt][2], acc[mt][nt][3]);
        }
    }
}

// OUT split-K=4: P[split] = O'(k-chunk) @ Wot.  grid (2 n, 32 m, 4 split)
__global__ __launch_bounds__(256, 2)
void out_kernel() {
    extern __shared__ char sm[];
    const int m0 = blockIdx.y * TM;
    const int n0 = blockIdx.x * TN;
    const int kbase = blockIdx.z * (FH / 4);
    float* P = g_P[blockIdx.z];

    float acc[4][4][4];
    run_gemm<(FH / 4) / BK>(sm,
        [&](int r, int k) {
            int kk = kbase + k;
            int h = kk >> 8, f = kk & 255;
            int rg = m0 + r;
            return g_O + (size_t)((rg >> 10) * H_ + h) * SF + (rg & 1023) * F_ + f;
        },
        [&](int r, int k) { return g_Wot + (size_t)(n0 + r) * FH + kbase + k; },
        acc);

    EPI_VARS();
#pragma unroll
    for (int mt = 0; mt < 4; mt++) {
        int r0 = m0 + wm + 16 * mt + g;
#pragma unroll
        for (int nt = 0; nt < 4; nt++) {
            int col = n0 + wn + nt * 8 + 2 * t;
            *(float2*)(P + (size_t)r0 * F_ + col) =
                make_float2(acc[mt][nt][0], acc[mt][nt][1]);
            *(float2*)(P + (size_t)(r0 + 8) * F_ + col) =
                make_float2(acc[mt][nt][2], acc[mt][nt][3]);
        }
    }
}

__global__ void reduce_relu_kernel(float* __restrict__ out) {
    const int i = blockIdx.x * 256 + threadIdx.x;
    float s = g_P[0][i] + g_P[1][i] + g_P[2][i] + g_P[3][i];
    out[i] = fmaxf(s, 0.f);
}

// ---------------------------------------------------------------------------
extern "C" void kernel_launch(void* const* d_in, const int* in_sizes, int n_in,
                              void* d_out, int out_size) {
    const float* q_input = (const float*)d_in[0];
    const float* Wq = (const float*)d_in[1];
    const float* Wk = (const float*)d_in[2];
    const float* Wv = (const float*)d_in[3];
    const float* Wo = (const float*)d_in[4];
    float* out = (float*)d_out;

    static bool attr_done = false;
    if (!attr_done) {
        cudaFuncSetAttribute(qkv_kernel, cudaFuncAttributeMaxDynamicSharedMemorySize, SMEM_TOTAL);
        cudaFuncSetAttribute(scores_kernel, cudaFuncAttributeMaxDynamicSharedMemorySize, SMEM_TOTAL);
        cudaFuncSetAttribute(av_kernel, cudaFuncAttributeMaxDynamicSharedMemorySize, SMEM_TOTAL);
        cudaFuncSetAttribute(out_kernel, cudaFuncAttributeMaxDynamicSharedMemorySize, SMEM_TOTAL);
        attr_done = true;
    }

    prep_x<<<ROWS * F_ / 256, 256>>>(q_input);
    { dim3 g(64, 8, 3), b(32, 8); prep_wqkv<<<g, b>>>(Wq, Wk, Wv); }
    prep_wo<<<FH, 256>>>(Wo);

    { dim3 g(FH / TN, ROWS / TM, 3); qkv_kernel<<<g, 256, SMEM_TOTAL>>>(); }   // (16,32,3)
    { dim3 g(32, 8, 32), b(32, 8); transpose_v<<<g, b>>>(); }
    { dim3 g(S_ / TN, S_ / TM, BH); scores_kernel<<<g, 256, SMEM_TOTAL>>>(); } // (8,8,32)
    { dim3 g(F_ / TN, S_ / TM, BH); av_kernel<<<g, 256, SMEM_TOTAL>>>(); }     // (2,8,32)
    { dim3 g(F_ / TN, ROWS / TM, 4); out_kernel<<<g, 256, SMEM_TOTAL>>>(); }   // (2,32,4)
    reduce_relu_kernel<<<ROWS * F_ / 256, 256>>>(out);
}

// round 8
// speedup vs baseline: 6.1960x; 1.0502x over previous
#include <cuda_runtime.h>
#include <cuda_fp16.h>
#include <cstdint>
#include <math.h>

// ---------------------------------------------------------------------------
// Problem constants
// ---------------------------------------------------------------------------
#define B_   4
#define S_   1024
#define F_   256
#define H_   8
#define ROWS 4096
#define FH   2048
#define BH   32
#define SF   262144            // S_*F_ per (b,h)
#define SS   1048576           // S_*S_ per (b,h)
#define SCALE 16.0f

#define BK   64                // k elems per smem stage (128 bytes fp16)
#define TM   128               // CTA tile M
#define TN   128               // CTA tile N
#define STAGE_BYTES 16384      // 128 rows * 128 B
#define BUF_BYTES   32768      // A stage + B stage
#define NSTAGE 3
#define SMEM_TOTAL  (NSTAGE * BUF_BYTES)   // 98304

// ---------------------------------------------------------------------------
// Scratch (__device__ globals; allocation-free)
// ---------------------------------------------------------------------------
__device__ __half g_X[ROWS * F_];
__device__ __half g_Wqt[FH * F_];       // [n=h*256+f][k]
__device__ __half g_Wkt[FH * F_];
__device__ __half g_Wvt[FH * F_];
__device__ __half g_Wot[F_ * FH];       // [n][kk=h*256+f]
__device__ __half g_Q[BH * SF];         // [b,h][s][f]
__device__ __half g_K[BH * SF];
__device__ __half g_V[BH * SF];
__device__ __half g_Vt[BH * SF];        // [b,h][f][s]
__device__ __half g_O[BH * SF];
__device__ __half g_S[(size_t)BH * SS]; // [b,h][i][j]
__device__ float  g_P[4][ROWS * F_];    // split-K partials

// ---------------------------------------------------------------------------
// PTX helpers
// ---------------------------------------------------------------------------
__device__ __forceinline__ uint32_t smem_u32(const void* p) {
    uint32_t a;
    asm("{ .reg .u64 t; cvta.to.shared.u64 t, %1; cvt.u32.u64 %0, t; }"
        : "=r"(a) : "l"(p));
    return a;
}

__device__ __forceinline__ void cp16(uint32_t dst, const void* src) {
    asm volatile("cp.async.cg.shared.global [%0], [%1], 16;\n"
                 :: "r"(dst), "l"(src));
}
#define CP_COMMIT() asm volatile("cp.async.commit_group;\n" ::: "memory")
#define CP_WAIT0()  asm volatile("cp.async.wait_group 0;\n" ::: "memory")
#define CP_WAIT1()  asm volatile("cp.async.wait_group 1;\n" ::: "memory")

__device__ __forceinline__ void mma16816(float d[4], const uint32_t a[4],
                                         const uint32_t b[2]) {
    asm volatile(
        "mma.sync.aligned.m16n8k16.row.col.f32.f16.f16.f32 "
        "{%0,%1,%2,%3},{%4,%5,%6,%7},{%8,%9},{%0,%1,%2,%3};\n"
        : "+f"(d[0]), "+f"(d[1]), "+f"(d[2]), "+f"(d[3])
        : "r"(a[0]), "r"(a[1]), "r"(a[2]), "r"(a[3]), "r"(b[0]), "r"(b[1]));
}

#define LDSM4(r0, r1, r2, r3, addr) \
    asm volatile("ldmatrix.sync.aligned.m8n8.x4.shared.b16 {%0,%1,%2,%3}, [%4];" \
                 : "=r"(r0), "=r"(r1), "=r"(r2), "=r"(r3) : "r"(addr))

// ---------------------------------------------------------------------------
// Tile fill: 128 rows x 64 fp16 (128B rows), chunk swizzle c ^ (row&7).
// p(row, kElem) -> const __half* (16B aligned)
// ---------------------------------------------------------------------------
template <class P>
__device__ __forceinline__ void issue_tile(uint32_t sbase, P p, int k0, int tid) {
#pragma unroll
    for (int it = 0; it < 4; it++) {
        int idx = tid + it * 256;
        int row = idx >> 3, c = idx & 7;
        uint32_t dst = sbase + row * 128 + ((c ^ (row & 7)) << 4);
        cp16(dst, p(row, k0 + c * 8));
    }
}

// ---------------------------------------------------------------------------
// One BK=64 stage: warp tile 64m x 32n, ldmatrix.x4 fragments.
// smem rows satisfy row&7 == lane&7 for all accessed rows (wm%64==0, wn%32==0),
// so the swizzle select is lane-uniform.
// ---------------------------------------------------------------------------
__device__ __forceinline__ void mma_stage(uint32_t Abase, uint32_t Bbase,
                                          int wm, int wn, int lane,
                                          float acc[4][4][4]) {
    const int l15 = lane & 15;
    const int l7 = lane & 7;
    const int hiA = lane >> 4;                 // 0/1 -> k-block select for A
    const int bm = lane >> 3;                  // 0..3 matrix id for B
    const int ntoff = (bm >> 1) << 3;          // 0 or 8
    const int chp = bm & 1;                    // 0/1 -> k-block select for B
#pragma unroll
    for (int kk = 0; kk < BK; kk += 16) {
        const int ch = kk >> 3;
        uint32_t a[4][4], b[4][2];
#pragma unroll
        for (int mt = 0; mt < 4; mt++) {
            int row = wm + 16 * mt + l15;
            uint32_t addr = Abase + row * 128 + ((uint32_t)((ch + hiA) ^ l7) << 4);
            LDSM4(a[mt][0], a[mt][1], a[mt][2], a[mt][3], addr);
        }
#pragma unroll
        for (int half = 0; half < 2; half++) {
            int row = wn + half * 16 + ntoff + l7;
            uint32_t addr = Bbase + row * 128 + ((uint32_t)((ch + chp) ^ l7) << 4);
            LDSM4(b[2 * half][0], b[2 * half][1],
                  b[2 * half + 1][0], b[2 * half + 1][1], addr);
        }
#pragma unroll
        for (int mt = 0; mt < 4; mt++)
#pragma unroll
            for (int nt = 0; nt < 4; nt++)
                mma16816(acc[mt][nt], a[mt], b[nt]);
    }
}

// Mainloop driver: NS stages, 3-deep cp.async pipeline
template <int NS, class PA, class PB>
__device__ __forceinline__ void run_gemm(char* sm, PA pa, PB pb,
                                         float acc[4][4][4]) {
    const int tid = threadIdx.x;
    const int w = tid >> 5, lane = tid & 31;
    const int wm = (w & 1) * 64, wn = (w >> 1) * 32;
    const uint32_t su = smem_u32(sm);

#pragma unroll
    for (int i = 0; i < 4; i++)
#pragma unroll
        for (int j = 0; j < 4; j++)
#pragma unroll
            for (int q = 0; q < 4; q++) acc[i][j][q] = 0.f;

    issue_tile(su, pa, 0, tid);
    issue_tile(su + STAGE_BYTES, pb, 0, tid);
    CP_COMMIT();
    issue_tile(su + BUF_BYTES, pa, BK, tid);
    issue_tile(su + BUF_BYTES + STAGE_BYTES, pb, BK, tid);
    CP_COMMIT();

    int buf = 0, nxt = 2;
#pragma unroll 1
    for (int s = 0; s < NS; s++) {
        if (s + 1 < NS) CP_WAIT1(); else CP_WAIT0();
        __syncthreads();
        if (s + 2 < NS) {
            uint32_t nb = su + nxt * BUF_BYTES;
            issue_tile(nb, pa, (s + 2) * BK, tid);
            issue_tile(nb + STAGE_BYTES, pb, (s + 2) * BK, tid);
            CP_COMMIT();
            nxt = (nxt == 2) ? 0 : nxt + 1;
        }
        mma_stage(su + buf * BUF_BYTES, su + buf * BUF_BYTES + STAGE_BYTES,
                  wm, wn, lane, acc);
        buf = (buf == 2) ? 0 : buf + 1;
        __syncthreads();
    }
}

// Epilogue vars: thread (g,t) of warp w; element (mt,nt): rows m0+wm+16mt+g(+8),
// cols n0+wn+8nt+2t(+1)
#define EPI_VARS()                               \
    const int tid = threadIdx.x;                 \
    const int w = tid >> 5, lane = tid & 31;     \
    const int g = lane >> 2, t = lane & 3;       \
    const int wm = (w & 1) * 64, wn = (w >> 1) * 32;

// ---------------------------------------------------------------------------
// Prep kernels
// ---------------------------------------------------------------------------
__global__ void prep_x(const float* __restrict__ X) {
    int i = blockIdx.x * 256 + threadIdx.x;
    g_X[i] = __float2half_rn(X[i]);
}

// W [k=256][c=f*8+h] -> Wt [n=h*256+f][k]
__global__ void prep_wqkv(const float* __restrict__ Wq,
                          const float* __restrict__ Wk,
                          const float* __restrict__ Wv) {
    __shared__ float T[32][33];
    const int z = blockIdx.z;
    const float* src = (z == 0) ? Wq : (z == 1) ? Wk : Wv;
    __half* dst = (z == 0) ? g_Wqt : (z == 1) ? g_Wkt : g_Wvt;
    const int c0 = blockIdx.x * 32, k0 = blockIdx.y * 32;
    const int tx = threadIdx.x, ty = threadIdx.y;
#pragma unroll
    for (int i = 0; i < 4; i++)
        T[ty + 8 * i][tx] = src[(size_t)(k0 + ty + 8 * i) * FH + c0 + tx];
    __syncthreads();
#pragma unroll
    for (int i = 0; i < 4; i++) {
        int c = c0 + ty + 8 * i;
        int n = (c & 7) * 256 + (c >> 3);
        dst[(size_t)n * F_ + k0 + tx] = __float2half_rn(T[tx][ty + 8 * i]);
    }
}

// Wo [row=f*8+h][n] -> Wot [n][kk=h*256+f]
__global__ void prep_wo(const float* __restrict__ Wo) {
    const int row = blockIdx.x;
    const int nn = threadIdx.x;
    int kk = ((row & 7) << 8) | (row >> 3);
    g_Wot[(size_t)nn * FH + kk] = __float2half_rn(Wo[(size_t)row * F_ + nn]);
}

// g_V [z][s][f] -> g_Vt [z][f][s]
__global__ void transpose_v() {
    __shared__ __half T[32][36];
    const size_t zoff = (size_t)blockIdx.z * SF;
    const int s0 = blockIdx.x * 32, f0 = blockIdx.y * 32;
    const int tx = threadIdx.x, ty = threadIdx.y;
#pragma unroll
    for (int i = 0; i < 4; i++)
        T[ty + 8 * i][tx] = g_V[zoff + (size_t)(s0 + ty + 8 * i) * F_ + f0 + tx];
    __syncthreads();
#pragma unroll
    for (int i = 0; i < 4; i++)
        g_Vt[zoff + (size_t)(f0 + ty + 8 * i) * S_ + s0 + tx] = T[tx][ty + 8 * i];
}

// ---------------------------------------------------------------------------
// GEMM kernels
// ---------------------------------------------------------------------------
// QKV: C[4096, 2048], A=g_X, B=Wt.  grid (16 n, 32 m, 3 z)
__global__ __launch_bounds__(256, 2)
void qkv_kernel() {
    extern __shared__ char sm[];
    const int m0 = blockIdx.y * TM;
    const int n0 = blockIdx.x * TN;
    const int z = blockIdx.z;
    const __half* Wt = (z == 0) ? g_Wqt : (z == 1) ? g_Wkt : g_Wvt;
    __half* dst = (z == 0) ? g_Q : (z == 1) ? g_K : g_V;
    const int h = n0 >> 8, f0 = n0 & 255;

    float acc[4][4][4];
    run_gemm<F_ / BK>(sm,
        [&](int r, int k) { return g_X + (size_t)(m0 + r) * F_ + k; },
        [&](int r, int k) { return Wt + (size_t)(n0 + r) * F_ + k; },
        acc);

    EPI_VARS();
#pragma unroll
    for (int mt = 0; mt < 4; mt++) {
        int r0 = m0 + wm + 16 * mt + g;
        __half* b0 = dst + (size_t)((r0 >> 10) * H_ + h) * SF + (r0 & 1023) * F_;
        __half* b1 = dst + (size_t)(((r0 + 8) >> 10) * H_ + h) * SF + ((r0 + 8) & 1023) * F_;
#pragma unroll
        for (int nt = 0; nt < 4; nt++) {
            int col = f0 + wn + nt * 8 + 2 * t;
            *(__half2*)(b0 + col) = __floats2half2_rn(acc[mt][nt][0], acc[mt][nt][1]);
            *(__half2*)(b1 + col) = __floats2half2_rn(acc[mt][nt][2], acc[mt][nt][3]);
        }
    }
}

// Scores: per z, S = sigmoid(16 * Q K^T).  grid (8 n, 8 m, 32 z)
__global__ __launch_bounds__(256, 2)
void scores_kernel() {
    extern __shared__ char sm[];
    const int m0 = blockIdx.y * TM;
    const int n0 = blockIdx.x * TN;
    const int z = blockIdx.z;
    const __half* Q = g_Q + (size_t)z * SF;
    const __half* Kp = g_K + (size_t)z * SF;
    __half* Sout = g_S + (size_t)z * SS;

    float acc[4][4][4];
    run_gemm<F_ / BK>(sm,
        [&](int r, int k) { return Q + (size_t)(m0 + r) * F_ + k; },
        [&](int r, int k) { return Kp + (size_t)(n0 + r) * F_ + k; },
        acc);

    EPI_VARS();
#pragma unroll
    for (int mt = 0; mt < 4; mt++) {
        int r0 = m0 + wm + 16 * mt + g;
#pragma unroll
        for (int nt = 0; nt < 4; nt++) {
            int col = n0 + wn + nt * 8 + 2 * t;
            float s0 = 1.f / (1.f + __expf(-SCALE * acc[mt][nt][0]));
            float s1 = 1.f / (1.f + __expf(-SCALE * acc[mt][nt][1]));
            float s2 = 1.f / (1.f + __expf(-SCALE * acc[mt][nt][2]));
            float s3 = 1.f / (1.f + __expf(-SCALE * acc[mt][nt][3]));
            *(__half2*)(Sout + (size_t)r0 * S_ + col) = __floats2half2_rn(s0, s1);
            *(__half2*)(Sout + (size_t)(r0 + 8) * S_ + col) = __floats2half2_rn(s2, s3);
        }
    }
}

// AV: per z, O = S @ V (B = Vt[f][s]).  grid (2 n, 8 m, 32 z)
__global__ __launch_bounds__(256, 2)
void av_kernel() {
    extern __shared__ char sm[];
    const int m0 = blockIdx.y * TM;
    const int n0 = blockIdx.x * TN;
    const int z = blockIdx.z;
    const __half* Sm = g_S + (size_t)z * SS;
    const __half* Vt = g_Vt + (size_t)z * SF;
    __half* O = g_O + (size_t)z * SF;

    float acc[4][4][4];
    run_gemm<S_ / BK>(sm,
        [&](int r, int k) { return Sm + (size_t)(m0 + r) * S_ + k; },
        [&](int r, int k) { return Vt + (size_t)(n0 + r) * S_ + k; },
        acc);

    EPI_VARS();
#pragma unroll
    for (int mt = 0; mt < 4; mt++) {
        int r0 = m0 + wm + 16 * mt + g;
#pragma unroll
        for (int nt = 0; nt < 4; nt++) {
            int col = n0 + wn + nt * 8 + 2 * t;
            *(__half2*)(O + (size_t)r0 * F_ + col) =
                __floats2half2_rn(acc[mt][nt][0], acc[mt][nt][1]);
            *(__half2*)(O + (size_t)(r0 + 8) * F_ + col) =
                __floats2half2_rn(acc[mt][nt][2], acc[mt][nt][3]);
        }
    }
}

// OUT split-K=4: P[split] = O'(k-chunk) @ Wot.  grid (2 n, 32 m, 4 split)
__global__ __launch_bounds__(256, 2)
void out_kernel() {
    extern __shared__ char sm[];
    const int m0 = blockIdx.y * TM;
    const int n0 = blockIdx.x * TN;
    const int kbase = blockIdx.z * (FH / 4);
    float* P = g_P[blockIdx.z];

    float acc[4][4][4];
    run_gemm<(FH / 4) / BK>(sm,
        [&](int r, int k) {
            int kk = kbase + k;
            int h = kk >> 8, f = kk & 255;
            int rg = m0 + r;
            return g_O + (size_t)((rg >> 10) * H_ + h) * SF + (rg & 1023) * F_ + f;
        },
        [&](int r, int k) { return g_Wot + (size_t)(n0 + r) * FH + kbase + k; },
        acc);

    EPI_VARS();
#pragma unroll
    for (int mt = 0; mt < 4; mt++) {
        int r0 = m0 + wm + 16 * mt + g;
#pragma unroll
        for (int nt = 0; nt < 4; nt++) {
            int col = n0 + wn + nt * 8 + 2 * t;
            *(float2*)(P + (size_t)r0 * F_ + col) =
                make_float2(acc[mt][nt][0], acc[mt][nt][1]);
            *(float2*)(P + (size_t)(r0 + 8) * F_ + col) =
                make_float2(acc[mt][nt][2], acc[mt][nt][3]);
        }
    }
}

__global__ void reduce_relu_kernel(float* __restrict__ out) {
    const int i = blockIdx.x * 256 + threadIdx.x;
    float s = g_P[0][i] + g_P[1][i] + g_P[2][i] + g_P[3][i];
    out[i] = fmaxf(s, 0.f);
}

// ---------------------------------------------------------------------------
extern "C" void kernel_launch(void* const* d_in, const int* in_sizes, int n_in,
                              void* d_out, int out_size) {
    const float* q_input = (const float*)d_in[0];
    const float* Wq = (const float*)d_in[1];
    const float* Wk = (const float*)d_in[2];
    const float* Wv = (const float*)d_in[3];
    const float* Wo = (const float*)d_in[4];
    float* out = (float*)d_out;

    cudaFuncSetAttribute(qkv_kernel, cudaFuncAttributeMaxDynamicSharedMemorySize, SMEM_TOTAL);
    cudaFuncSetAttribute(scores_kernel, cudaFuncAttributeMaxDynamicSharedMemorySize, SMEM_TOTAL);
    cudaFuncSetAttribute(av_kernel, cudaFuncAttributeMaxDynamicSharedMemorySize, SMEM_TOTAL);
    cudaFuncSetAttribute(out_kernel, cudaFuncAttributeMaxDynamicSharedMemorySize, SMEM_TOTAL);

    prep_x<<<ROWS * F_ / 256, 256>>>(q_input);
    { dim3 g(64, 8, 3), b(32, 8); prep_wqkv<<<g, b>>>(Wq, Wk, Wv); }
    prep_wo<<<FH, 256>>>(Wo);

    { dim3 g(FH / TN, ROWS / TM, 3); qkv_kernel<<<g, 256, SMEM_TOTAL>>>(); }   // (16,32,3)
    { dim3 g(32, 8, 32), b(32, 8); transpose_v<<<g, b>>>(); }
    { dim3 g(S_ / TN, S_ / TM, BH); scores_kernel<<<g, 256, SMEM_TOTAL>>>(); } // (8,8,32)
    { dim3 g(F_ / TN, S_ / TM, BH); av_kernel<<<g, 256, SMEM_TOTAL>>>(); }     // (2,8,32)
    { dim3 g(F_ / TN, ROWS / TM, 4); out_kernel<<<g, 256, SMEM_TOTAL>>>(); }   // (2,32,4)
    reduce_relu_kernel<<<ROWS * F_ / 256, 256>>>(out);
}

// round 10
// speedup vs baseline: 6.5254x; 1.0532x over previous
#include <cuda_runtime.h>
#include <cuda_fp16.h>
#include <cstdint>
#include <math.h>

// ---------------------------------------------------------------------------
// Problem constants
// ---------------------------------------------------------------------------
#define B_   4
#define S_   1024
#define F_   256
#define H_   8
#define ROWS 4096
#define FH   2048
#define BH   32
#define SF   262144            // S_*F_ per (b,h)
#define SS   1048576           // S_*S_ per (b,h)
#define SCALE 16.0f

#define BK   64                // k elems per smem stage (128 bytes fp16)
#define SMEM_BIG  98304        // 3 * (128*128 + 128*128) bytes
#define SMEM_AV   73728        // 3 * (64*128 + 128*128) bytes

// ---------------------------------------------------------------------------
// Scratch (__device__ globals; allocation-free)
// ---------------------------------------------------------------------------
__device__ __half g_X[ROWS * F_];
__device__ __half g_Wqt[FH * F_];       // [n=h*256+f][k]
__device__ __half g_Wkt[FH * F_];
__device__ __half g_Wvt[FH * F_];
__device__ __half g_Wot[F_ * FH];       // [n][kk=h*256+f]
__device__ __half g_Q[BH * SF];         // [b,h][s][f]
__device__ __half g_K[BH * SF];
__device__ __half g_Vt[BH * SF];        // [b,h][f][s]
__device__ __half g_O[BH * SF];
__device__ __half g_S[(size_t)BH * SS]; // [b,h][i][j]
__device__ float  g_P[4][ROWS * F_];    // split-K partials

// ---------------------------------------------------------------------------
// PTX helpers
// ---------------------------------------------------------------------------
__device__ __forceinline__ uint32_t smem_u32(const void* p) {
    uint32_t a;
    asm("{ .reg .u64 t; cvta.to.shared.u64 t, %1; cvt.u32.u64 %0, t; }"
        : "=r"(a) : "l"(p));
    return a;
}

__device__ __forceinline__ void cp16(uint32_t dst, const void* src) {
    asm volatile("cp.async.cg.shared.global [%0], [%1], 16;\n"
                 :: "r"(dst), "l"(src));
}
#define CP_COMMIT() asm volatile("cp.async.commit_group;\n" ::: "memory")
#define CP_WAIT0()  asm volatile("cp.async.wait_group 0;\n" ::: "memory")
#define CP_WAIT1()  asm volatile("cp.async.wait_group 1;\n" ::: "memory")

__device__ __forceinline__ void mma16816(float d[4], const uint32_t a[4],
                                         const uint32_t b[2]) {
    asm volatile(
        "mma.sync.aligned.m16n8k16.row.col.f32.f16.f16.f32 "
        "{%0,%1,%2,%3},{%4,%5,%6,%7},{%8,%9},{%0,%1,%2,%3};\n"
        : "+f"(d[0]), "+f"(d[1]), "+f"(d[2]), "+f"(d[3])
        : "r"(a[0]), "r"(a[1]), "r"(a[2]), "r"(a[3]), "r"(b[0]), "r"(b[1]));
}

#define LDSM4(r0, r1, r2, r3, addr) \
    asm volatile("ldmatrix.sync.aligned.m8n8.x4.shared.b16 {%0,%1,%2,%3}, [%4];" \
                 : "=r"(r0), "=r"(r1), "=r"(r2), "=r"(r3) : "r"(addr))

// ---------------------------------------------------------------------------
// Tile fill: NR rows x 64 fp16 (128B rows), chunk swizzle c ^ (row&7).
// ---------------------------------------------------------------------------
template <int NR, class P>
__device__ __forceinline__ void issue_tile(uint32_t sbase, P p, int k0, int tid) {
#pragma unroll
    for (int it = 0; it < NR * 8 / 256; it++) {
        int idx = tid + it * 256;
        int row = idx >> 3, c = idx & 7;
        uint32_t dst = sbase + row * 128 + ((c ^ (row & 7)) << 4);
        cp16(dst, p(row, k0 + c * 8));
    }
}

// ---------------------------------------------------------------------------
// One BK=64 stage: warp tile (16*MT) x 32, ldmatrix.x4 fragments.
// ---------------------------------------------------------------------------
template <int MT>
__device__ __forceinline__ void mma_stage(uint32_t Abase, uint32_t Bbase,
                                          int wm, int wn, int lane,
                                          float acc[][4][4]) {
    const int l15 = lane & 15;
    const int l7 = lane & 7;
    const int hiA = lane >> 4;
    const int bm = lane >> 3;
    const int ntoff = (bm >> 1) << 3;
    const int chp = bm & 1;
#pragma unroll
    for (int kk = 0; kk < BK; kk += 16) {
        const int ch = kk >> 3;
        uint32_t a[MT][4], b[4][2];
#pragma unroll
        for (int mt = 0; mt < MT; mt++) {
            int row = wm + 16 * mt + l15;
            uint32_t addr = Abase + row * 128 + ((uint32_t)((ch + hiA) ^ l7) << 4);
            LDSM4(a[mt][0], a[mt][1], a[mt][2], a[mt][3], addr);
        }
#pragma unroll
        for (int half = 0; half < 2; half++) {
            int row = wn + half * 16 + ntoff + l7;
            uint32_t addr = Bbase + row * 128 + ((uint32_t)((ch + chp) ^ l7) << 4);
            LDSM4(b[2 * half][0], b[2 * half][1],
                  b[2 * half + 1][0], b[2 * half + 1][1], addr);
        }
#pragma unroll
        for (int mt = 0; mt < MT; mt++)
#pragma unroll
            for (int nt = 0; nt < 4; nt++)
                mma16816(acc[mt][nt], a[mt], b[nt]);
    }
}

// ---------------------------------------------------------------------------
// Mainloop driver: NS stages, 3-deep cp.async pipeline. A tile = AM x 64,
// B tile = 128 x 64. One barrier per stage.
// ---------------------------------------------------------------------------
template <int NS, int AM, int MT, class PA, class PB>
__device__ __forceinline__ void run_gemm(char* sm, PA pa, PB pb,
                                         float acc[][4][4]) {
    const int tid = threadIdx.x;
    const int w = tid >> 5, lane = tid & 31;
    const int wm = (w & 1) * (16 * MT), wn = (w >> 1) * 32;
    const uint32_t su = smem_u32(sm);
    constexpr uint32_t ABYTES = AM * 128;
    constexpr uint32_t BUFB = ABYTES + 16384;

#pragma unroll
    for (int i = 0; i < MT; i++)
#pragma unroll
        for (int j = 0; j < 4; j++)
#pragma unroll
            for (int q = 0; q < 4; q++) acc[i][j][q] = 0.f;

    issue_tile<AM>(su, pa, 0, tid);
    issue_tile<128>(su + ABYTES, pb, 0, tid);
    CP_COMMIT();
    issue_tile<AM>(su + BUFB, pa, BK, tid);
    issue_tile<128>(su + BUFB + ABYTES, pb, BK, tid);
    CP_COMMIT();

    int buf = 0, nxt = 2;
#pragma unroll 1
    for (int s = 0; s < NS; s++) {
        if (s + 1 < NS) CP_WAIT1(); else CP_WAIT0();
        __syncthreads();
        if (s + 2 < NS) {
            uint32_t nb = su + nxt * BUFB;
            issue_tile<AM>(nb, pa, (s + 2) * BK, tid);
            issue_tile<128>(nb + ABYTES, pb, (s + 2) * BK, tid);
            CP_COMMIT();
            nxt = (nxt == 2) ? 0 : nxt + 1;
        }
        mma_stage<MT>(su + buf * BUFB, su + buf * BUFB + ABYTES,
                      wm, wn, lane, acc);
        buf = (buf == 2) ? 0 : buf + 1;
    }
}

#define EPI_VARS(MT_)                            \
    const int tid = threadIdx.x;                 \
    const int w = tid >> 5, lane = tid & 31;     \
    const int g = lane >> 2, t = lane & 3;       \
    const int wm = (w & 1) * (16 * (MT_)), wn = (w >> 1) * 32;

// ---------------------------------------------------------------------------
// Prep kernels
// ---------------------------------------------------------------------------
// z=0: X fp32->fp16 ; z=1: Wo permute rows to kk=h*256+f
__global__ void prep_misc(const float* __restrict__ X,
                          const float* __restrict__ Wo) {
    const int i = blockIdx.x * 256 + threadIdx.x;
    if (blockIdx.y == 0) {
        g_X[i] = __float2half_rn(X[i]);
    } else if (i < FH * F_) {
        int row = i >> 8, nn = i & 255;
        int kk = ((row & 7) << 8) | (row >> 3);
        g_Wot[(size_t)nn * FH + kk] = __float2half_rn(Wo[(size_t)row * F_ + nn]);
    }
}

// W [k=256][c=f*8+h] -> Wt [n=h*256+f][k]
__global__ void prep_wqkv(const float* __restrict__ Wq,
                          const float* __restrict__ Wk,
                          const float* __restrict__ Wv) {
    __shared__ float T[32][33];
    const int z = blockIdx.z;
    const float* src = (z == 0) ? Wq : (z == 1) ? Wk : Wv;
    __half* dst = (z == 0) ? g_Wqt : (z == 1) ? g_Wkt : g_Wvt;
    const int c0 = blockIdx.x * 32, k0 = blockIdx.y * 32;
    const int tx = threadIdx.x, ty = threadIdx.y;
#pragma unroll
    for (int i = 0; i < 4; i++)
        T[ty + 8 * i][tx] = src[(size_t)(k0 + ty + 8 * i) * FH + c0 + tx];
    __syncthreads();
#pragma unroll
    for (int i = 0; i < 4; i++) {
        int c = c0 + ty + 8 * i;
        int n = (c & 7) * 256 + (c >> 3);
        dst[(size_t)n * F_ + k0 + tx] = __float2half_rn(T[tx][ty + 8 * i]);
    }
}

// ---------------------------------------------------------------------------
// QKV: C[4096, 2048], A=g_X, B=Wt.  grid (16 n, 32 m, 3 z)
// z=0/1 -> Q/K in [b,h][s][f];  z=2 -> V written TRANSPOSED to g_Vt [b,h][f][s]
// via smem staging (pad-136 tile).
// ---------------------------------------------------------------------------
__global__ __launch_bounds__(256, 2)
void qkv_kernel() {
    extern __shared__ char sm[];
    const int m0 = blockIdx.y * 128;
    const int n0 = blockIdx.x * 128;
    const int z = blockIdx.z;
    const __half* Wt = (z == 0) ? g_Wqt : (z == 1) ? g_Wkt : g_Wvt;
    const int h = n0 >> 8, f0 = n0 & 255;

    float acc[4][4][4];
    run_gemm<F_ / BK, 128, 4>(sm,
        [&](int r, int k) { return g_X + (size_t)(m0 + r) * F_ + k; },
        [&](int r, int k) { return Wt + (size_t)(n0 + r) * F_ + k; },
        acc);

    EPI_VARS(4);
    if (z != 2) {
        __half* dst = (z == 0) ? g_Q : g_K;
#pragma unroll
        for (int mt = 0; mt < 4; mt++) {
            int r0 = m0 + wm + 16 * mt + g;
            __half* b0 = dst + (size_t)((r0 >> 10) * H_ + h) * SF + (r0 & 1023) * F_;
            __half* b1 = b0 + 8 * F_;       // r0+8 stays in same 1024-row batch
#pragma unroll
            for (int nt = 0; nt < 4; nt++) {
                int col = f0 + wn + nt * 8 + 2 * t;
                *(__half2*)(b0 + col) = __floats2half2_rn(acc[mt][nt][0], acc[mt][nt][1]);
                *(__half2*)(b1 + col) = __floats2half2_rn(acc[mt][nt][2], acc[mt][nt][3]);
            }
        }
    } else {
        // stage transposed tile in smem: tile[f_col][s_row], stride 136 halves
        __syncthreads();
        __half* tile = (__half*)sm;
#pragma unroll
        for (int mt = 0; mt < 4; mt++) {
            int lr = wm + 16 * mt + g;
#pragma unroll
            for (int nt = 0; nt < 4; nt++) {
                int cl = wn + 8 * nt + 2 * t;
                tile[(size_t)cl * 136 + lr]           = __float2half_rn(acc[mt][nt][0]);
                tile[(size_t)(cl + 1) * 136 + lr]     = __float2half_rn(acc[mt][nt][1]);
                tile[(size_t)cl * 136 + lr + 8]       = __float2half_rn(acc[mt][nt][2]);
                tile[(size_t)(cl + 1) * 136 + lr + 8] = __float2half_rn(acc[mt][nt][3]);
            }
        }
        __syncthreads();
        // drain: 128 f-rows x 16 chunks of 8 halves = full 128x128 tile
        __half* base = g_Vt + (size_t)((m0 >> 10) * H_ + h) * SF + (m0 & 1023);
#pragma unroll
        for (int it = 0; it < 8; it++) {
            int idx = tid + it * 256;           // 0..2047
            int fr = idx >> 4, ch = idx & 15;
            uint4 v = *(const uint4*)&tile[(size_t)fr * 136 + ch * 8];
            *(uint4*)&base[(size_t)(f0 + fr) * S_ + ch * 8] = v;
        }
    }
}

// ---------------------------------------------------------------------------
// Scores: per z, S = sigmoid(16 * Q K^T).  grid (8 n, 8 m, 32 z)
// ---------------------------------------------------------------------------
__global__ __launch_bounds__(256, 2)
void scores_kernel() {
    extern __shared__ char sm[];
    const int m0 = blockIdx.y * 128;
    const int n0 = blockIdx.x * 128;
    const int z = blockIdx.z;
    const __half* Q = g_Q + (size_t)z * SF;
    const __half* Kp = g_K + (size_t)z * SF;
    __half* Sout = g_S + (size_t)z * SS;

    float acc[4][4][4];
    run_gemm<F_ / BK, 128, 4>(sm,
        [&](int r, int k) { return Q + (size_t)(m0 + r) * F_ + k; },
        [&](int r, int k) { return Kp + (size_t)(n0 + r) * F_ + k; },
        acc);

    EPI_VARS(4);
#pragma unroll
    for (int mt = 0; mt < 4; mt++) {
        int r0 = m0 + wm + 16 * mt + g;
#pragma unroll
        for (int nt = 0; nt < 4; nt++) {
            int col = n0 + wn + nt * 8 + 2 * t;
            float s0 = 1.f / (1.f + __expf(-SCALE * acc[mt][nt][0]));
            float s1 = 1.f / (1.f + __expf(-SCALE * acc[mt][nt][1]));
            float s2 = 1.f / (1.f + __expf(-SCALE * acc[mt][nt][2]));
            float s3 = 1.f / (1.f + __expf(-SCALE * acc[mt][nt][3]));
            *(__half2*)(Sout + (size_t)r0 * S_ + col) = __floats2half2_rn(s0, s1);
            *(__half2*)(Sout + (size_t)(r0 + 8) * S_ + col) = __floats2half2_rn(s2, s3);
        }
    }
}

// ---------------------------------------------------------------------------
// AV: per z, O = S @ V (B = Vt[f][s]).  TM=64 tiles: grid (2 n, 16 m, 32 z)
// ---------------------------------------------------------------------------
__global__ __launch_bounds__(256, 2)
void av_kernel() {
    extern __shared__ char sm[];
    const int m0 = blockIdx.y * 64;
    const int n0 = blockIdx.x * 128;
    const int z = blockIdx.z;
    const __half* Sm = g_S + (size_t)z * SS;
    const __half* Vt = g_Vt + (size_t)z * SF;
    __half* O = g_O + (size_t)z * SF;

    float acc[2][4][4];
    run_gemm<S_ / BK, 64, 2>(sm,
        [&](int r, int k) { return Sm + (size_t)(m0 + r) * S_ + k; },
        [&](int r, int k) { return Vt + (size_t)(n0 + r) * S_ + k; },
        acc);

    EPI_VARS(2);
#pragma unroll
    for (int mt = 0; mt < 2; mt++) {
        int r0 = m0 + wm + 16 * mt + g;
#pragma unroll
        for (int nt = 0; nt < 4; nt++) {
            int col = n0 + wn + nt * 8 + 2 * t;
            *(__half2*)(O + (size_t)r0 * F_ + col) =
                __floats2half2_rn(acc[mt][nt][0], acc[mt][nt][1]);
            *(__half2*)(O + (size_t)(r0 + 8) * F_ + col) =
                __floats2half2_rn(acc[mt][nt][2], acc[mt][nt][3]);
        }
    }
}

// ---------------------------------------------------------------------------
// OUT split-K=4: P[split] = O'(k-chunk) @ Wot.  grid (2 n, 32 m, 4 split)
// ---------------------------------------------------------------------------
__global__ __launch_bounds__(256, 2)
void out_kernel() {
    extern __shared__ char sm[];
    const int m0 = blockIdx.y * 128;
    const int n0 = blockIdx.x * 128;
    const int kbase = blockIdx.z * (FH / 4);
    float* P = g_P[blockIdx.z];

    float acc[4][4][4];
    run_gemm<(FH / 4) / BK, 128, 4>(sm,
        [&](int r, int k) {
            int kk = kbase + k;
            int h = kk >> 8, f = kk & 255;
            int rg = m0 + r;
            return g_O + (size_t)((rg >> 10) * H_ + h) * SF + (rg & 1023) * F_ + f;
        },
        [&](int r, int k) { return g_Wot + (size_t)(n0 + r) * FH + kbase + k; },
        acc);

    EPI_VARS(4);
#pragma unroll
    for (int mt = 0; mt < 4; mt++) {
        int r0 = m0 + wm + 16 * mt + g;
#pragma unroll
        for (int nt = 0; nt < 4; nt++) {
            int col = n0 + wn + nt * 8 + 2 * t;
            *(float2*)(P + (size_t)r0 * F_ + col) =
                make_float2(acc[mt][nt][0], acc[mt][nt][1]);
            *(float2*)(P + (size_t)(r0 + 8) * F_ + col) =
                make_float2(acc[mt][nt][2], acc[mt][nt][3]);
        }
    }
}

__global__ void reduce_relu_kernel(float* __restrict__ out) {
    const int i = blockIdx.x * 256 + threadIdx.x;
    float s = g_P[0][i] + g_P[1][i] + g_P[2][i] + g_P[3][i];
    out[i] = fmaxf(s, 0.f);
}

// ---------------------------------------------------------------------------
extern "C" void kernel_launch(void* const* d_in, const int* in_sizes, int n_in,
                              void* d_out, int out_size) {
    const float* q_input = (const float*)d_in[0];
    const float* Wq = (const float*)d_in[1];
    const float* Wk = (const float*)d_in[2];
    const float* Wv = (const float*)d_in[3];
    const float* Wo = (const float*)d_in[4];
    float* out = (float*)d_out;

    cudaFuncSetAttribute(qkv_kernel, cudaFuncAttributeMaxDynamicSharedMemorySize, SMEM_BIG);
    cudaFuncSetAttribute(scores_kernel, cudaFuncAttributeMaxDynamicSharedMemorySize, SMEM_BIG);
    cudaFuncSetAttribute(av_kernel, cudaFuncAttributeMaxDynamicSharedMemorySize, SMEM_AV);
    cudaFuncSetAttribute(out_kernel, cudaFuncAttributeMaxDynamicSharedMemorySize, SMEM_BIG);

    { dim3 g(4096, 2); prep_misc<<<g, 256>>>(q_input, Wo); }
    { dim3 g(64, 8, 3), b(32, 8); prep_wqkv<<<g, b>>>(Wq, Wk, Wv); }

    { dim3 g(16, 32, 3); qkv_kernel<<<g, 256, SMEM_BIG>>>(); }
    { dim3 g(8, 8, 32); scores_kernel<<<g, 256, SMEM_BIG>>>(); }
    { dim3 g(2, 16, 32); av_kernel<<<g, 256, SMEM_AV>>>(); }
    { dim3 g(2, 32, 4); out_kernel<<<g, 256, SMEM_BIG>>>(); }
    reduce_relu_kernel<<<ROWS * F_ / 256, 256>>>(out);
}

// round 12
// speedup vs baseline: 6.8301x; 1.0467x over previous
#include <cuda_runtime.h>
#include <cuda_fp16.h>
#include <cstdint>
#include <math.h>

// ---------------------------------------------------------------------------
// Problem constants
// ---------------------------------------------------------------------------
#define B_   4
#define S_   1024
#define F_   256
#define H_   8
#define ROWS 4096
#define FH   2048
#define BH   32
#define SF   262144            // S_*F_ per (b,h)
#define SS   1048576           // S_*S_ per (b,h)

#define BK   64                // k elems per smem stage (128 bytes fp16)
// All GEMMs: TM=64 (MT=2), TN=128. Buffer = (64+128)*128B = 24576.
#define SMEM_ALL  73728        // 3 buffers

// ---------------------------------------------------------------------------
// Scratch (__device__ globals; allocation-free)
// ---------------------------------------------------------------------------
__device__ __half g_X[ROWS * F_];
__device__ __half g_Wqt[FH * F_];       // [n=h*256+f][k]
__device__ __half g_Wkt[FH * F_];
__device__ __half g_Wvt[FH * F_];
__device__ __half g_Wot[F_ * FH];       // [n][kk=h*256+f]
__device__ __half g_Q[BH * SF];         // [b,h][s][f]
__device__ __half g_K[BH * SF];
__device__ __half g_Vt[BH * SF];        // [b,h][f][s]
__device__ __half g_O[BH * SF];
__device__ __half g_S[(size_t)BH * SS]; // [b,h][i][j]
__device__ float  g_P[4][ROWS * F_];    // split-K partials

// ---------------------------------------------------------------------------
// PTX helpers
// ---------------------------------------------------------------------------
__device__ __forceinline__ uint32_t smem_u32(const void* p) {
    uint32_t a;
    asm("{ .reg .u64 t; cvta.to.shared.u64 t, %1; cvt.u32.u64 %0, t; }"
        : "=r"(a) : "l"(p));
    return a;
}

__device__ __forceinline__ void cp16(uint32_t dst, const void* src) {
    asm volatile("cp.async.cg.shared.global [%0], [%1], 16;\n"
                 :: "r"(dst), "l"(src));
}
#define CP_COMMIT() asm volatile("cp.async.commit_group;\n" ::: "memory")
#define CP_WAIT0()  asm volatile("cp.async.wait_group 0;\n" ::: "memory")
#define CP_WAIT1()  asm volatile("cp.async.wait_group 1;\n" ::: "memory")

__device__ __forceinline__ void mma16816(float d[4], const uint32_t a[4],
                                         const uint32_t b[2]) {
    asm volatile(
        "mma.sync.aligned.m16n8k16.row.col.f32.f16.f16.f32 "
        "{%0,%1,%2,%3},{%4,%5,%6,%7},{%8,%9},{%0,%1,%2,%3};\n"
        : "+f"(d[0]), "+f"(d[1]), "+f"(d[2]), "+f"(d[3])
        : "r"(a[0]), "r"(a[1]), "r"(a[2]), "r"(a[3]), "r"(b[0]), "r"(b[1]));
}

#define LDSM4(r0, r1, r2, r3, addr) \
    asm volatile("ldmatrix.sync.aligned.m8n8.x4.shared.b16 {%0,%1,%2,%3}, [%4];" \
                 : "=r"(r0), "=r"(r1), "=r"(r2), "=r"(r3) : "r"(addr))

// sigmoid(16x) = 0.5 + 0.5*tanh(8x)  (tanh.approx: 1 MUFU)
__device__ __forceinline__ float sigm16(float x) {
    float t;
    asm("tanh.approx.f32 %0, %1;" : "=f"(t) : "f"(8.0f * x));
    return 0.5f + 0.5f * t;
}

// ---------------------------------------------------------------------------
// Tile fill: NR rows x 64 fp16 (128B rows), chunk swizzle c ^ (row&7).
// ---------------------------------------------------------------------------
template <int NR, class P>
__device__ __forceinline__ void issue_tile(uint32_t sbase, P p, int k0, int tid) {
#pragma unroll
    for (int it = 0; it < NR * 8 / 256; it++) {
        int idx = tid + it * 256;
        int row = idx >> 3, c = idx & 7;
        uint32_t dst = sbase + row * 128 + ((c ^ (row & 7)) << 4);
        cp16(dst, p(row, k0 + c * 8));
    }
}

// ---------------------------------------------------------------------------
// One BK=64 stage: warp tile 32 x 32, ldmatrix.x4 fragments.
// ---------------------------------------------------------------------------
__device__ __forceinline__ void mma_stage(uint32_t Abase, uint32_t Bbase,
                                          int wm, int wn, int lane,
                                          float acc[2][4][4]) {
    const int l15 = lane & 15;
    const int l7 = lane & 7;
    const int hiA = lane >> 4;
    const int bm = lane >> 3;
    const int ntoff = (bm >> 1) << 3;
    const int chp = bm & 1;
#pragma unroll
    for (int kk = 0; kk < BK; kk += 16) {
        const int ch = kk >> 3;
        uint32_t a[2][4], b[4][2];
#pragma unroll
        for (int mt = 0; mt < 2; mt++) {
            int row = wm + 16 * mt + l15;
            uint32_t addr = Abase + row * 128 + ((uint32_t)((ch + hiA) ^ l7) << 4);
            LDSM4(a[mt][0], a[mt][1], a[mt][2], a[mt][3], addr);
        }
#pragma unroll
        for (int half = 0; half < 2; half++) {
            int row = wn + half * 16 + ntoff + l7;
            uint32_t addr = Bbase + row * 128 + ((uint32_t)((ch + chp) ^ l7) << 4);
            LDSM4(b[2 * half][0], b[2 * half][1],
                  b[2 * half + 1][0], b[2 * half + 1][1], addr);
        }
#pragma unroll
        for (int mt = 0; mt < 2; mt++)
#pragma unroll
            for (int nt = 0; nt < 4; nt++)
                mma16816(acc[mt][nt], a[mt], b[nt]);
    }
}

// ---------------------------------------------------------------------------
// Mainloop: NS stages, 3-deep cp.async pipeline. A = 64 x 64, B = 128 x 64.
// ---------------------------------------------------------------------------
template <int NS, class PA, class PB>
__device__ __forceinline__ void run_gemm(char* sm, PA pa, PB pb,
                                         float acc[2][4][4]) {
    const int tid = threadIdx.x;
    const int w = tid >> 5, lane = tid & 31;
    const int wm = (w & 1) * 32, wn = (w >> 1) * 32;
    const uint32_t su = smem_u32(sm);
    constexpr uint32_t ABYTES = 64 * 128;
    constexpr uint32_t BUFB = ABYTES + 16384;   // 24576

#pragma unroll
    for (int i = 0; i < 2; i++)
#pragma unroll
        for (int j = 0; j < 4; j++)
#pragma unroll
            for (int q = 0; q < 4; q++) acc[i][j][q] = 0.f;

    issue_tile<64>(su, pa, 0, tid);
    issue_tile<128>(su + ABYTES, pb, 0, tid);
    CP_COMMIT();
    issue_tile<64>(su + BUFB, pa, BK, tid);
    issue_tile<128>(su + BUFB + ABYTES, pb, BK, tid);
    CP_COMMIT();

    int buf = 0, nxt = 2;
#pragma unroll 1
    for (int s = 0; s < NS; s++) {
        if (s + 1 < NS) CP_WAIT1(); else CP_WAIT0();
        __syncthreads();
        if (s + 2 < NS) {
            uint32_t nb = su + nxt * BUFB;
            issue_tile<64>(nb, pa, (s + 2) * BK, tid);
            issue_tile<128>(nb + ABYTES, pb, (s + 2) * BK, tid);
            CP_COMMIT();
            nxt = (nxt == 2) ? 0 : nxt + 1;
        }
        mma_stage(su + buf * BUFB, su + buf * BUFB + ABYTES, wm, wn, lane, acc);
        buf = (buf == 2) ? 0 : buf + 1;
    }
}

#define EPI_VARS()                               \
    const int tid = threadIdx.x;                 \
    const int w = tid >> 5, lane = tid & 31;     \
    const int g = lane >> 2, t = lane & 3;       \
    const int wm = (w & 1) * 32, wn = (w >> 1) * 32;

// ---------------------------------------------------------------------------
// Prep kernels
// ---------------------------------------------------------------------------
__global__ void prep_misc(const float* __restrict__ X,
                          const float* __restrict__ Wo) {
    const int i = blockIdx.x * 256 + threadIdx.x;
    if (blockIdx.y == 0) {
        g_X[i] = __float2half_rn(X[i]);
    } else if (i < FH * F_) {
        int row = i >> 8, nn = i & 255;
        int kk = ((row & 7) << 8) | (row >> 3);
        g_Wot[(size_t)nn * FH + kk] = __float2half_rn(Wo[(size_t)row * F_ + nn]);
    }
}

// W [k=256][c=f*8+h] -> Wt [n=h*256+f][k]
__global__ void prep_wqkv(const float* __restrict__ Wq,
                          const float* __restrict__ Wk,
                          const float* __restrict__ Wv) {
    __shared__ float T[32][33];
    const int z = blockIdx.z;
    const float* src = (z == 0) ? Wq : (z == 1) ? Wk : Wv;
    __half* dst = (z == 0) ? g_Wqt : (z == 1) ? g_Wkt : g_Wvt;
    const int c0 = blockIdx.x * 32, k0 = blockIdx.y * 32;
    const int tx = threadIdx.x, ty = threadIdx.y;
#pragma unroll
    for (int i = 0; i < 4; i++)
        T[ty + 8 * i][tx] = src[(size_t)(k0 + ty + 8 * i) * FH + c0 + tx];
    __syncthreads();
#pragma unroll
    for (int i = 0; i < 4; i++) {
        int c = c0 + ty + 8 * i;
        int n = (c & 7) * 256 + (c >> 3);
        dst[(size_t)n * F_ + k0 + tx] = __float2half_rn(T[tx][ty + 8 * i]);
    }
}

// ---------------------------------------------------------------------------
// QKV: C[4096, 2048], A=g_X, B=Wt.  grid (16 n, 64 m, 3 z)
// z=0/1 -> Q/K in [b,h][s][f];  z=2 -> V transposed into g_Vt [b,h][f][s]
// ---------------------------------------------------------------------------
__global__ __launch_bounds__(256, 3)
void qkv_kernel() {
    extern __shared__ char sm[];
    const int m0 = blockIdx.y * 64;
    const int n0 = blockIdx.x * 128;
    const int z = blockIdx.z;
    const __half* Wt = (z == 0) ? g_Wqt : (z == 1) ? g_Wkt : g_Wvt;
    const int h = n0 >> 8, f0 = n0 & 255;

    float acc[2][4][4];
    run_gemm<F_ / BK>(sm,
        [&](int r, int k) { return g_X + (size_t)(m0 + r) * F_ + k; },
        [&](int r, int k) { return Wt + (size_t)(n0 + r) * F_ + k; },
        acc);

    EPI_VARS();
    if (z != 2) {
        __half* dst = (z == 0) ? g_Q : g_K;
#pragma unroll
        for (int mt = 0; mt < 2; mt++) {
            int r0 = m0 + wm + 16 * mt + g;
            __half* b0 = dst + (size_t)((r0 >> 10) * H_ + h) * SF + (r0 & 1023) * F_;
            __half* b1 = b0 + 8 * F_;
#pragma unroll
            for (int nt = 0; nt < 4; nt++) {
                int col = f0 + wn + nt * 8 + 2 * t;
                *(__half2*)(b0 + col) = __floats2half2_rn(acc[mt][nt][0], acc[mt][nt][1]);
                *(__half2*)(b1 + col) = __floats2half2_rn(acc[mt][nt][2], acc[mt][nt][3]);
            }
        }
    } else {
        // stage transposed tile: tile[f_col (128)][s_row (64), pad to 72]
        __syncthreads();
        __half* tile = (__half*)sm;
#pragma unroll
        for (int mt = 0; mt < 2; mt++) {
            int lr = wm + 16 * mt + g;
#pragma unroll
            for (int nt = 0; nt < 4; nt++) {
                int cl = wn + 8 * nt + 2 * t;
                tile[(size_t)cl * 72 + lr]           = __float2half_rn(acc[mt][nt][0]);
                tile[(size_t)(cl + 1) * 72 + lr]     = __float2half_rn(acc[mt][nt][1]);
                tile[(size_t)cl * 72 + lr + 8]       = __float2half_rn(acc[mt][nt][2]);
                tile[(size_t)(cl + 1) * 72 + lr + 8] = __float2half_rn(acc[mt][nt][3]);
            }
        }
        __syncthreads();
        // drain: 128 f-rows x 8 chunks of 8 halves = 128 x 64 tile
        __half* base = g_Vt + (size_t)((m0 >> 10) * H_ + h) * SF + (m0 & 1023);
#pragma unroll
        for (int it = 0; it < 4; it++) {
            int idx = tid + it * 256;           // 0..1023
            int fr = idx >> 3, ch = idx & 7;
            uint4 v = *(const uint4*)&tile[(size_t)fr * 72 + ch * 8];
            *(uint4*)&base[(size_t)(f0 + fr) * S_ + ch * 8] = v;
        }
    }
}

// ---------------------------------------------------------------------------
// Scores: per z, S = sigmoid(16 * Q K^T).  grid (8 n, 16 m, 32 z)
// ---------------------------------------------------------------------------
__global__ __launch_bounds__(256, 3)
void scores_kernel() {
    extern __shared__ char sm[];
    const int m0 = blockIdx.y * 64;
    const int n0 = blockIdx.x * 128;
    const int z = blockIdx.z;
    const __half* Q = g_Q + (size_t)z * SF;
    const __half* Kp = g_K + (size_t)z * SF;
    __half* Sout = g_S + (size_t)z * SS;

    float acc[2][4][4];
    run_gemm<F_ / BK>(sm,
        [&](int r, int k) { return Q + (size_t)(m0 + r) * F_ + k; },
        [&](int r, int k) { return Kp + (size_t)(n0 + r) * F_ + k; },
        acc);

    EPI_VARS();
#pragma unroll
    for (int mt = 0; mt < 2; mt++) {
        int r0 = m0 + wm + 16 * mt + g;
#pragma unroll
        for (int nt = 0; nt < 4; nt++) {
            int col = n0 + wn + nt * 8 + 2 * t;
            *(__half2*)(Sout + (size_t)r0 * S_ + col) =
                __floats2half2_rn(sigm16(acc[mt][nt][0]), sigm16(acc[mt][nt][1]));
            *(__half2*)(Sout + (size_t)(r0 + 8) * S_ + col) =
                __floats2half2_rn(sigm16(acc[mt][nt][2]), sigm16(acc[mt][nt][3]));
        }
    }
}

// ---------------------------------------------------------------------------
// AV: per z, O = S @ V (B = Vt[f][s]).  grid (2 n, 16 m, 32 z)
// ---------------------------------------------------------------------------
__global__ __launch_bounds__(256, 3)
void av_kernel() {
    extern __shared__ char sm[];
    const int m0 = blockIdx.y * 64;
    const int n0 = blockIdx.x * 128;
    const int z = blockIdx.z;
    const __half* Sm = g_S + (size_t)z * SS;
    const __half* Vt = g_Vt + (size_t)z * SF;
    __half* O = g_O + (size_t)z * SF;

    float acc[2][4][4];
    run_gemm<S_ / BK>(sm,
        [&](int r, int k) { return Sm + (size_t)(m0 + r) * S_ + k; },
        [&](int r, int k) { return Vt + (size_t)(n0 + r) * S_ + k; },
        acc);

    EPI_VARS();
#pragma unroll
    for (int mt = 0; mt < 2; mt++) {
        int r0 = m0 + wm + 16 * mt + g;
#pragma unroll
        for (int nt = 0; nt < 4; nt++) {
            int col = n0 + wn + nt * 8 + 2 * t;
            *(__half2*)(O + (size_t)r0 * F_ + col) =
                __floats2half2_rn(acc[mt][nt][0], acc[mt][nt][1]);
            *(__half2*)(O + (size_t)(r0 + 8) * F_ + col) =
                __floats2half2_rn(acc[mt][nt][2], acc[mt][nt][3]);
        }
    }
}

// ---------------------------------------------------------------------------
// OUT split-K=4: P[split] = O'(k-chunk) @ Wot.  grid (2 n, 64 m, 4 split)
// ---------------------------------------------------------------------------
__global__ __launch_bounds__(256, 3)
void out_kernel() {
    extern __shared__ char sm[];
    const int m0 = blockIdx.y * 64;
    const int n0 = blockIdx.x * 128;
    const int kbase = blockIdx.z * (FH / 4);
    float* P = g_P[blockIdx.z];

    float acc[2][4][4];
    run_gemm<(FH / 4) / BK>(sm,
        [&](int r, int k) {
            int kk = kbase + k;
            int h = kk >> 8, f = kk & 255;
            int rg = m0 + r;
            return g_O + (size_t)((rg >> 10) * H_ + h) * SF + (rg & 1023) * F_ + f;
        },
        [&](int r, int k) { return g_Wot + (size_t)(n0 + r) * FH + kbase + k; },
        acc);

    EPI_VARS();
#pragma unroll
    for (int mt = 0; mt < 2; mt++) {
        int r0 = m0 + wm + 16 * mt + g;
#pragma unroll
        for (int nt = 0; nt < 4; nt++) {
            int col = n0 + wn + nt * 8 + 2 * t;
            *(float2*)(P + (size_t)r0 * F_ + col) =
                make_float2(acc[mt][nt][0], acc[mt][nt][1]);
            *(float2*)(P + (size_t)(r0 + 8) * F_ + col) =
                make_float2(acc[mt][nt][2], acc[mt][nt][3]);
        }
    }
}

__global__ void reduce_relu_kernel(float* __restrict__ out) {
    const int i = blockIdx.x * 256 + threadIdx.x;
    float s = g_P[0][i] + g_P[1][i] + g_P[2][i] + g_P[3][i];
    out[i] = fmaxf(s, 0.f);
}

// ---------------------------------------------------------------------------
extern "C" void kernel_launch(void* const* d_in, const int* in_sizes, int n_in,
                              void* d_out, int out_size) {
    const float* q_input = (const float*)d_in[0];
    const float* Wq = (const float*)d_in[1];
    const float* Wk = (const float*)d_in[2];
    const float* Wv = (const float*)d_in[3];
    const float* Wo = (const float*)d_in[4];
    float* out = (float*)d_out;

    cudaFuncSetAttribute(qkv_kernel, cudaFuncAttributeMaxDynamicSharedMemorySize, SMEM_ALL);
    cudaFuncSetAttribute(scores_kernel, cudaFuncAttributeMaxDynamicSharedMemorySize, SMEM_ALL);
    cudaFuncSetAttribute(av_kernel, cudaFuncAttributeMaxDynamicSharedMemorySize, SMEM_ALL);
    cudaFuncSetAttribute(out_kernel, cudaFuncAttributeMaxDynamicSharedMemorySize, SMEM_ALL);

    { dim3 g(4096, 2); prep_misc<<<g, 256>>>(q_input, Wo); }
    { dim3 g(64, 8, 3), b(32, 8); prep_wqkv<<<g, b>>>(Wq, Wk, Wv); }

    { dim3 g(16, 64, 3); qkv_kernel<<<g, 256, SMEM_ALL>>>(); }
    { dim3 g(8, 16, 32); scores_kernel<<<g, 256, SMEM_ALL>>>(); }
    { dim3 g(2, 16, 32); av_kernel<<<g, 256, SMEM_ALL>>>(); }
    { dim3 g(2, 64, 4); out_kernel<<<g, 256, SMEM_ALL>>>(); }
    reduce_relu_kernel<<<ROWS * F_ / 256, 256>>>(out);
}

// round 13
// speedup vs baseline: 6.8346x; 1.0007x over previous
#include <cuda_runtime.h>
#include <cuda_fp16.h>
#include <cstdint>
#include <math.h>

// ---------------------------------------------------------------------------
// Problem constants
// ---------------------------------------------------------------------------
#define B_   4
#define S_   1024
#define F_   256
#define H_   8
#define ROWS 4096
#define FH   2048
#define BH   32
#define SF   262144            // S_*F_ per (b,h)
#define SS   1048576           // S_*S_ per (b,h)

#define BK   64                // k elems per smem stage (128 bytes fp16)
// All GEMMs: TM=64 (MT=2), TN=128. Buffer = (64+128)*128B = 24576.
#define SMEM_ALL  73728        // 3 buffers
#define KSPLIT 8

// ---------------------------------------------------------------------------
// Scratch (__device__ globals; allocation-free)
// ---------------------------------------------------------------------------
__device__ __half g_X[ROWS * F_];
__device__ __half g_Wqt[FH * F_];       // [n=h*256+f][k]
__device__ __half g_Wkt[FH * F_];
__device__ __half g_Wvt[FH * F_];
__device__ __half g_Wot[F_ * FH];       // [n][kk=h*256+f]
__device__ __half g_Q[BH * SF];         // [b,h][s][f]
__device__ __half g_K[BH * SF];
__device__ __half g_Vt[BH * SF];        // [b,h][f][s]
__device__ __half g_O[BH * SF];
__device__ __half g_S[(size_t)BH * SS]; // [b,h][i][j]
__device__ float  g_P[KSPLIT][ROWS * F_]; // split-K partials

// ---------------------------------------------------------------------------
// PTX helpers
// ---------------------------------------------------------------------------
__device__ __forceinline__ uint32_t smem_u32(const void* p) {
    uint32_t a;
    asm("{ .reg .u64 t; cvta.to.shared.u64 t, %1; cvt.u32.u64 %0, t; }"
        : "=r"(a) : "l"(p));
    return a;
}

__device__ __forceinline__ void cp16(uint32_t dst, const void* src) {
    asm volatile("cp.async.cg.shared.global [%0], [%1], 16;\n"
                 :: "r"(dst), "l"(src));
}
#define CP_COMMIT() asm volatile("cp.async.commit_group;\n" ::: "memory")
#define CP_WAIT0()  asm volatile("cp.async.wait_group 0;\n" ::: "memory")
#define CP_WAIT1()  asm volatile("cp.async.wait_group 1;\n" ::: "memory")

__device__ __forceinline__ void mma16816(float d[4], const uint32_t a[4],
                                         const uint32_t b[2]) {
    asm volatile(
        "mma.sync.aligned.m16n8k16.row.col.f32.f16.f16.f32 "
        "{%0,%1,%2,%3},{%4,%5,%6,%7},{%8,%9},{%0,%1,%2,%3};\n"
        : "+f"(d[0]), "+f"(d[1]), "+f"(d[2]), "+f"(d[3])
        : "r"(a[0]), "r"(a[1]), "r"(a[2]), "r"(a[3]), "r"(b[0]), "r"(b[1]));
}

#define LDSM4(r0, r1, r2, r3, addr) \
    asm volatile("ldmatrix.sync.aligned.m8n8.x4.shared.b16 {%0,%1,%2,%3}, [%4];" \
                 : "=r"(r0), "=r"(r1), "=r"(r2), "=r"(r3) : "r"(addr))

// sigmoid(16x) = 0.5 + 0.5*tanh(8x)  (tanh.approx: 1 MUFU)
__device__ __forceinline__ float sigm16(float x) {
    float t;
    asm("tanh.approx.f32 %0, %1;" : "=f"(t) : "f"(8.0f * x));
    return 0.5f + 0.5f * t;
}

// ---------------------------------------------------------------------------
// Tile fill: NR rows x 64 fp16 (128B rows), chunk swizzle c ^ (row&7).
// ---------------------------------------------------------------------------
template <int NR, class P>
__device__ __forceinline__ void issue_tile(uint32_t sbase, P p, int k0, int tid) {
#pragma unroll
    for (int it = 0; it < NR * 8 / 256; it++) {
        int idx = tid + it * 256;
        int row = idx >> 3, c = idx & 7;
        uint32_t dst = sbase + row * 128 + ((c ^ (row & 7)) << 4);
        cp16(dst, p(row, k0 + c * 8));
    }
}

// ---------------------------------------------------------------------------
// One BK=64 stage: warp tile 32 x 32, ldmatrix.x4 fragments.
// ---------------------------------------------------------------------------
__device__ __forceinline__ void mma_stage(uint32_t Abase, uint32_t Bbase,
                                          int wm, int wn, int lane,
                                          float acc[2][4][4]) {
    const int l15 = lane & 15;
    const int l7 = lane & 7;
    const int hiA = lane >> 4;
    const int bm = lane >> 3;
    const int ntoff = (bm >> 1) << 3;
    const int chp = bm & 1;
#pragma unroll
    for (int kk = 0; kk < BK; kk += 16) {
        const int ch = kk >> 3;
        uint32_t a[2][4], b[4][2];
#pragma unroll
        for (int mt = 0; mt < 2; mt++) {
            int row = wm + 16 * mt + l15;
            uint32_t addr = Abase + row * 128 + ((uint32_t)((ch + hiA) ^ l7) << 4);
            LDSM4(a[mt][0], a[mt][1], a[mt][2], a[mt][3], addr);
        }
#pragma unroll
        for (int half = 0; half < 2; half++) {
            int row = wn + half * 16 + ntoff + l7;
            uint32_t addr = Bbase + row * 128 + ((uint32_t)((ch + chp) ^ l7) << 4);
            LDSM4(b[2 * half][0], b[2 * half][1],
                  b[2 * half + 1][0], b[2 * half + 1][1], addr);
        }
#pragma unroll
        for (int mt = 0; mt < 2; mt++)
#pragma unroll
            for (int nt = 0; nt < 4; nt++)
                mma16816(acc[mt][nt], a[mt], b[nt]);
    }
}

// ---------------------------------------------------------------------------
// Mainloop: NS stages, 3-deep cp.async pipeline. A = 64 x 64, B = 128 x 64.
// ---------------------------------------------------------------------------
template <int NS, class PA, class PB>
__device__ __forceinline__ void run_gemm(char* sm, PA pa, PB pb,
                                         float acc[2][4][4]) {
    const int tid = threadIdx.x;
    const int w = tid >> 5, lane = tid & 31;
    const int wm = (w & 1) * 32, wn = (w >> 1) * 32;
    const uint32_t su = smem_u32(sm);
    constexpr uint32_t ABYTES = 64 * 128;
    constexpr uint32_t BUFB = ABYTES + 16384;   // 24576

#pragma unroll
    for (int i = 0; i < 2; i++)
#pragma unroll
        for (int j = 0; j < 4; j++)
#pragma unroll
            for (int q = 0; q < 4; q++) acc[i][j][q] = 0.f;

    issue_tile<64>(su, pa, 0, tid);
    issue_tile<128>(su + ABYTES, pb, 0, tid);
    CP_COMMIT();
    issue_tile<64>(su + BUFB, pa, BK, tid);
    issue_tile<128>(su + BUFB + ABYTES, pb, BK, tid);
    CP_COMMIT();

    int buf = 0, nxt = 2;
#pragma unroll 1
    for (int s = 0; s < NS; s++) {
        if (s + 1 < NS) CP_WAIT1(); else CP_WAIT0();
        __syncthreads();
        if (s + 2 < NS) {
            uint32_t nb = su + nxt * BUFB;
            issue_tile<64>(nb, pa, (s + 2) * BK, tid);
            issue_tile<128>(nb + ABYTES, pb, (s + 2) * BK, tid);
            CP_COMMIT();
            nxt = (nxt == 2) ? 0 : nxt + 1;
        }
        mma_stage(su + buf * BUFB, su + buf * BUFB + ABYTES, wm, wn, lane, acc);
        buf = (buf == 2) ? 0 : buf + 1;
    }
}

#define EPI_VARS()                               \
    const int tid = threadIdx.x;                 \
    const int w = tid >> 5, lane = tid & 31;     \
    const int g = lane >> 2, t = lane & 3;       \
    const int wm = (w & 1) * 32, wn = (w >> 1) * 32;

// ---------------------------------------------------------------------------
// Prep kernels
// ---------------------------------------------------------------------------
__global__ void prep_misc(const float* __restrict__ X,
                          const float* __restrict__ Wo) {
    const int i = blockIdx.x * 256 + threadIdx.x;
    if (blockIdx.y == 0) {
        g_X[i] = __float2half_rn(X[i]);
        // second half of X handled by upper blocks; Wo by y==1 grid half
        int i2 = i + ROWS * F_ / 2;
        (void)i2;
    } else {
        if (i < FH * F_) {
            int row = i >> 8, nn = i & 255;
            int kk = ((row & 7) << 8) | (row >> 3);
            g_Wot[(size_t)nn * FH + kk] = __float2half_rn(Wo[(size_t)row * F_ + nn]);
        }
    }
}

// W [k=256][c=f*8+h] -> Wt [n=h*256+f][k]
__global__ void prep_wqkv(const float* __restrict__ Wq,
                          const float* __restrict__ Wk,
                          const float* __restrict__ Wv) {
    __shared__ float T[32][33];
    const int z = blockIdx.z;
    const float* src = (z == 0) ? Wq : (z == 1) ? Wk : Wv;
    __half* dst = (z == 0) ? g_Wqt : (z == 1) ? g_Wkt : g_Wvt;
    const int c0 = blockIdx.x * 32, k0 = blockIdx.y * 32;
    const int tx = threadIdx.x, ty = threadIdx.y;
#pragma unroll
    for (int i = 0; i < 4; i++)
        T[ty + 8 * i][tx] = src[(size_t)(k0 + ty + 8 * i) * FH + c0 + tx];
    __syncthreads();
#pragma unroll
    for (int i = 0; i < 4; i++) {
        int c = c0 + ty + 8 * i;
        int n = (c & 7) * 256 + (c >> 3);
        dst[(size_t)n * F_ + k0 + tx] = __float2half_rn(T[tx][ty + 8 * i]);
    }
}

// ---------------------------------------------------------------------------
// QKV: C[4096, 2048], A=g_X, B=Wt.  grid (16 n, 64 m, 3 z)
// z=0/1 -> Q/K in [b,h][s][f];  z=2 -> V transposed into g_Vt [b,h][f][s]
// ---------------------------------------------------------------------------
__global__ __launch_bounds__(256, 3)
void qkv_kernel() {
    extern __shared__ char sm[];
    const int m0 = blockIdx.y * 64;
    const int n0 = blockIdx.x * 128;
    const int z = blockIdx.z;
    const __half* Wt = (z == 0) ? g_Wqt : (z == 1) ? g_Wkt : g_Wvt;
    const int h = n0 >> 8, f0 = n0 & 255;

    float acc[2][4][4];
    run_gemm<F_ / BK>(sm,
        [&](int r, int k) { return g_X + (size_t)(m0 + r) * F_ + k; },
        [&](int r, int k) { return Wt + (size_t)(n0 + r) * F_ + k; },
        acc);

    EPI_VARS();
    if (z != 2) {
        __half* dst = (z == 0) ? g_Q : g_K;
#pragma unroll
        for (int mt = 0; mt < 2; mt++) {
            int r0 = m0 + wm + 16 * mt + g;
            __half* b0 = dst + (size_t)((r0 >> 10) * H_ + h) * SF + (r0 & 1023) * F_;
            __half* b1 = b0 + 8 * F_;
#pragma unroll
            for (int nt = 0; nt < 4; nt++) {
                int col = f0 + wn + nt * 8 + 2 * t;
                *(__half2*)(b0 + col) = __floats2half2_rn(acc[mt][nt][0], acc[mt][nt][1]);
                *(__half2*)(b1 + col) = __floats2half2_rn(acc[mt][nt][2], acc[mt][nt][3]);
            }
        }
    } else {
        // stage transposed tile: tile[f_col (128)][s_row (64), pad to 72]
        __syncthreads();
        __half* tile = (__half*)sm;
#pragma unroll
        for (int mt = 0; mt < 2; mt++) {
            int lr = wm + 16 * mt + g;
#pragma unroll
            for (int nt = 0; nt < 4; nt++) {
                int cl = wn + 8 * nt + 2 * t;
                tile[(size_t)cl * 72 + lr]           = __float2half_rn(acc[mt][nt][0]);
                tile[(size_t)(cl + 1) * 72 + lr]     = __float2half_rn(acc[mt][nt][1]);
                tile[(size_t)cl * 72 + lr + 8]       = __float2half_rn(acc[mt][nt][2]);
                tile[(size_t)(cl + 1) * 72 + lr + 8] = __float2half_rn(acc[mt][nt][3]);
            }
        }
        __syncthreads();
        // drain: 128 f-rows x 8 chunks of 8 halves = 128 x 64 tile
        __half* base = g_Vt + (size_t)((m0 >> 10) * H_ + h) * SF + (m0 & 1023);
#pragma unroll
        for (int it = 0; it < 4; it++) {
            int idx = tid + it * 256;           // 0..1023
            int fr = idx >> 3, ch = idx & 7;
            uint4 v = *(const uint4*)&tile[(size_t)fr * 72 + ch * 8];
            *(uint4*)&base[(size_t)(f0 + fr) * S_ + ch * 8] = v;
        }
    }
}

// ---------------------------------------------------------------------------
// Scores: per z, S = sigmoid(16 * Q K^T).  grid (8 n, 16 m, 32 z)
// ---------------------------------------------------------------------------
__global__ __launch_bounds__(256, 3)
void scores_kernel() {
    extern __shared__ char sm[];
    const int m0 = blockIdx.y * 64;
    const int n0 = blockIdx.x * 128;
    const int z = blockIdx.z;
    const __half* Q = g_Q + (size_t)z * SF;
    const __half* Kp = g_K + (size_t)z * SF;
    __half* Sout = g_S + (size_t)z * SS;

    float acc[2][4][4];
    run_gemm<F_ / BK>(sm,
        [&](int r, int k) { return Q + (size_t)(m0 + r) * F_ + k; },
        [&](int r, int k) { return Kp + (size_t)(n0 + r) * F_ + k; },
        acc);

    EPI_VARS();
#pragma unroll
    for (int mt = 0; mt < 2; mt++) {
        int r0 = m0 + wm + 16 * mt + g;
#pragma unroll
        for (int nt = 0; nt < 4; nt++) {
            int col = n0 + wn + nt * 8 + 2 * t;
            *(__half2*)(Sout + (size_t)r0 * S_ + col) =
                __floats2half2_rn(sigm16(acc[mt][nt][0]), sigm16(acc[mt][nt][1]));
            *(__half2*)(Sout + (size_t)(r0 + 8) * S_ + col) =
                __floats2half2_rn(sigm16(acc[mt][nt][2]), sigm16(acc[mt][nt][3]));
        }
    }
}

// ---------------------------------------------------------------------------
// AV: per z, O = S @ V (B = Vt[f][s]).  grid (2 n, 16 m, 32 z)
// ---------------------------------------------------------------------------
__global__ __launch_bounds__(256, 3)
void av_kernel() {
    extern __shared__ char sm[];
    const int m0 = blockIdx.y * 64;
    const int n0 = blockIdx.x * 128;
    const int z = blockIdx.z;
    const __half* Sm = g_S + (size_t)z * SS;
    const __half* Vt = g_Vt + (size_t)z * SF;
    __half* O = g_O + (size_t)z * SF;

    float acc[2][4][4];
    run_gemm<S_ / BK>(sm,
        [&](int r, int k) { return Sm + (size_t)(m0 + r) * S_ + k; },
        [&](int r, int k) { return Vt + (size_t)(n0 + r) * S_ + k; },
        acc);

    EPI_VARS();
#pragma unroll
    for (int mt = 0; mt < 2; mt++) {
        int r0 = m0 + wm + 16 * mt + g;
#pragma unroll
        for (int nt = 0; nt < 4; nt++) {
            int col = n0 + wn + nt * 8 + 2 * t;
            *(__half2*)(O + (size_t)r0 * F_ + col) =
                __floats2half2_rn(acc[mt][nt][0], acc[mt][nt][1]);
            *(__half2*)(O + (size_t)(r0 + 8) * F_ + col) =
                __floats2half2_rn(acc[mt][nt][2], acc[mt][nt][3]);
        }
    }
}

// ---------------------------------------------------------------------------
// OUT split-K=8: P[split] = O'(k-chunk) @ Wot.  grid (2 n, 64 m, 8 split)
// ---------------------------------------------------------------------------
__global__ __launch_bounds__(256, 3)
void out_kernel() {
    extern __shared__ char sm[];
    const int m0 = blockIdx.y * 64;
    const int n0 = blockIdx.x * 128;
    const int kbase = blockIdx.z * (FH / KSPLIT);
    float* P = g_P[blockIdx.z];

    float acc[2][4][4];
    run_gemm<(FH / KSPLIT) / BK>(sm,
        [&](int r, int k) {
            int kk = kbase + k;
            int h = kk >> 8, f = kk & 255;
            int rg = m0 + r;
            return g_O + (size_t)((rg >> 10) * H_ + h) * SF + (rg & 1023) * F_ + f;
        },
        [&](int r, int k) { return g_Wot + (size_t)(n0 + r) * FH + kbase + k; },
        acc);

    EPI_VARS();
#pragma unroll
    for (int mt = 0; mt < 2; mt++) {
        int r0 = m0 + wm + 16 * mt + g;
#pragma unroll
        for (int nt = 0; nt < 4; nt++) {
            int col = n0 + wn + nt * 8 + 2 * t;
            *(float2*)(P + (size_t)r0 * F_ + col) =
                make_float2(acc[mt][nt][0], acc[mt][nt][1]);
            *(float2*)(P + (size_t)(r0 + 8) * F_ + col) =
                make_float2(acc[mt][nt][2], acc[mt][nt][3]);
        }
    }
}

__global__ void reduce_relu_kernel(float* __restrict__ out) {
    const int i = (blockIdx.x * 256 + threadIdx.x) * 4;
    float4 s = *(const float4*)&g_P[0][i];
#pragma unroll
    for (int p = 1; p < KSPLIT; p++) {
        float4 v = *(const float4*)&g_P[p][i];
        s.x += v.x; s.y += v.y; s.z += v.z; s.w += v.w;
    }
    s.x = fmaxf(s.x, 0.f); s.y = fmaxf(s.y, 0.f);
    s.z = fmaxf(s.z, 0.f); s.w = fmaxf(s.w, 0.f);
    *(float4*)&out[i] = s;
}

// ---------------------------------------------------------------------------
extern "C" void kernel_launch(void* const* d_in, const int* in_sizes, int n_in,
                              void* d_out, int out_size) {
    const float* q_input = (const float*)d_in[0];
    const float* Wq = (const float*)d_in[1];
    const float* Wk = (const float*)d_in[2];
    const float* Wv = (const float*)d_in[3];
    const float* Wo = (const float*)d_in[4];
    float* out = (float*)d_out;

    cudaFuncSetAttribute(qkv_kernel, cudaFuncAttributeMaxDynamicSharedMemorySize, SMEM_ALL);
    cudaFuncSetAttribute(scores_kernel, cudaFuncAttributeMaxDynamicSharedMemorySize, SMEM_ALL);
    cudaFuncSetAttribute(av_kernel, cudaFuncAttributeMaxDynamicSharedMemorySize, SMEM_ALL);
    cudaFuncSetAttribute(out_kernel, cudaFuncAttributeMaxDynamicSharedMemorySize, SMEM_ALL);

    { dim3 g(4096, 2); prep_misc<<<g, 256>>>(q_input, Wo); }
    { dim3 g(64, 8, 3), b(32, 8); prep_wqkv<<<g, b>>>(Wq, Wk, Wv); }

    { dim3 g(16, 64, 3); qkv_kernel<<<g, 256, SMEM_ALL>>>(); }
    { dim3 g(8, 16, 32); scores_kernel<<<g, 256, SMEM_ALL>>>(); }
    { dim3 g(2, 16, 32); av_kernel<<<g, 256, SMEM_ALL>>>(); }
    { dim3 g(2, 64, KSPLIT); out_kernel<<<g, 256, SMEM_ALL>>>(); }
    reduce_relu_kernel<<<ROWS * F_ / 1024, 256>>>(out);
}

// round 16
// speedup vs baseline: 6.8929x; 1.0085x over previous
#include <cuda_runtime.h>
#include <cuda_fp16.h>
#include <cstdint>
#include <math.h>

// ---------------------------------------------------------------------------
// Problem constants
// ---------------------------------------------------------------------------
#define B_   4
#define S_   1024
#define F_   256
#define H_   8
#define ROWS 4096
#define FH   2048
#define BH   32
#define SF   262144            // S_*F_ per (b,h)
#define SS   1048576           // S_*S_ per (b,h)

#define BK   64                // k elems per smem stage (128 bytes fp16)
// All GEMMs: TM=64 (MT=2), TN=128. Buffer = (64+128)*128B = 24576.
#define SMEM_ALL  73728        // 3 buffers
#define KSPLIT 4

// ---------------------------------------------------------------------------
// Scratch (__device__ globals; allocation-free)
// ---------------------------------------------------------------------------
__device__ __half g_X[ROWS * F_];
__device__ __half g_Wqt[FH * F_];       // [n=h*256+f][k]
__device__ __half g_Wkt[FH * F_];
__device__ __half g_Wvt[FH * F_];
__device__ __half g_Wot[F_ * FH];       // [n][kk=h*256+f]
__device__ __half g_Q[BH * SF];         // [b,h][s][f]
__device__ __half g_K[BH * SF];
__device__ __half g_Vt[BH * SF];        // [b,h][f][s]
__device__ __half g_O[BH * SF];
__device__ __half g_S[(size_t)BH * SS]; // [b,h][i][j]
__device__ float  g_P[KSPLIT][ROWS * F_]; // split-K partials

// ---------------------------------------------------------------------------
// PTX helpers
// ---------------------------------------------------------------------------
__device__ __forceinline__ uint32_t smem_u32(const void* p) {
    uint32_t a;
    asm("{ .reg .u64 t; cvta.to.shared.u64 t, %1; cvt.u32.u64 %0, t; }"
        : "=r"(a) : "l"(p));
    return a;
}

__device__ __forceinline__ void cp16(uint32_t dst, const void* src) {
    asm volatile("cp.async.cg.shared.global [%0], [%1], 16;\n"
                 :: "r"(dst), "l"(src));
}
#define CP_COMMIT() asm volatile("cp.async.commit_group;\n" ::: "memory")
#define CP_WAIT0()  asm volatile("cp.async.wait_group 0;\n" ::: "memory")
#define CP_WAIT1()  asm volatile("cp.async.wait_group 1;\n" ::: "memory")

__device__ __forceinline__ void mma16816(float d[4], const uint32_t a[4],
                                         const uint32_t b[2]) {
    asm volatile(
        "mma.sync.aligned.m16n8k16.row.col.f32.f16.f16.f32 "
        "{%0,%1,%2,%3},{%4,%5,%6,%7},{%8,%9},{%0,%1,%2,%3};\n"
        : "+f"(d[0]), "+f"(d[1]), "+f"(d[2]), "+f"(d[3])
        : "r"(a[0]), "r"(a[1]), "r"(a[2]), "r"(a[3]), "r"(b[0]), "r"(b[1]));
}

#define LDSM4(r0, r1, r2, r3, addr) \
    asm volatile("ldmatrix.sync.aligned.m8n8.x4.shared.b16 {%0,%1,%2,%3}, [%4];" \
                 : "=r"(r0), "=r"(r1), "=r"(r2), "=r"(r3) : "r"(addr))

// sigmoid(16x) = 0.5 + 0.5*tanh(8x)  (tanh.approx: 1 MUFU)
__device__ __forceinline__ float sigm16(float x) {
    float t;
    asm("tanh.approx.f32 %0, %1;" : "=f"(t) : "f"(8.0f * x));
    return 0.5f + 0.5f * t;
}

// ---------------------------------------------------------------------------
// Tile fill: NR rows x 64 fp16 (128B rows), chunk swizzle c ^ (row&7).
// ---------------------------------------------------------------------------
template <int NR, class P>
__device__ __forceinline__ void issue_tile(uint32_t sbase, P p, int k0, int tid) {
#pragma unroll
    for (int it = 0; it < NR * 8 / 256; it++) {
        int idx = tid + it * 256;
        int row = idx >> 3, c = idx & 7;
        uint32_t dst = sbase + row * 128 + ((c ^ (row & 7)) << 4);
        cp16(dst, p(row, k0 + c * 8));
    }
}

// ---------------------------------------------------------------------------
// One BK=64 stage: warp tile 32 x 32, ldmatrix.x4 fragments.
// ---------------------------------------------------------------------------
__device__ __forceinline__ void mma_stage(uint32_t Abase, uint32_t Bbase,
                                          int wm, int wn, int lane,
                                          float acc[2][4][4]) {
    const int l15 = lane & 15;
    const int l7 = lane & 7;
    const int hiA = lane >> 4;
    const int bm = lane >> 3;
    const int ntoff = (bm >> 1) << 3;
    const int chp = bm & 1;
#pragma unroll
    for (int kk = 0; kk < BK; kk += 16) {
        const int ch = kk >> 3;
        uint32_t a[2][4], b[4][2];
#pragma unroll
        for (int mt = 0; mt < 2; mt++) {
            int row = wm + 16 * mt + l15;
            uint32_t addr = Abase + row * 128 + ((uint32_t)((ch + hiA) ^ l7) << 4);
            LDSM4(a[mt][0], a[mt][1], a[mt][2], a[mt][3], addr);
        }
#pragma unroll
        for (int half = 0; half < 2; half++) {
            int row = wn + half * 16 + ntoff + l7;
            uint32_t addr = Bbase + row * 128 + ((uint32_t)((ch + chp) ^ l7) << 4);
            LDSM4(b[2 * half][0], b[2 * half][1],
                  b[2 * half + 1][0], b[2 * half + 1][1], addr);
        }
#pragma unroll
        for (int mt = 0; mt < 2; mt++)
#pragma unroll
            for (int nt = 0; nt < 4; nt++)
                mma16816(acc[mt][nt], a[mt], b[nt]);
    }
}

// ---------------------------------------------------------------------------
// Mainloop: NS stages, 3-deep cp.async pipeline. A = 64 x 64, B = 128 x 64.
// ---------------------------------------------------------------------------
template <int NS, class PA, class PB>
__device__ __forceinline__ void run_gemm(char* sm, PA pa, PB pb,
                                         float acc[2][4][4]) {
    const int tid = threadIdx.x;
    const int w = tid >> 5, lane = tid & 31;
    const int wm = (w & 1) * 32, wn = (w >> 1) * 32;
    const uint32_t su = smem_u32(sm);
    constexpr uint32_t ABYTES = 64 * 128;
    constexpr uint32_t BUFB = ABYTES + 16384;   // 24576

#pragma unroll
    for (int i = 0; i < 2; i++)
#pragma unroll
        for (int j = 0; j < 4; j++)
#pragma unroll
            for (int q = 0; q < 4; q++) acc[i][j][q] = 0.f;

    issue_tile<64>(su, pa, 0, tid);
    issue_tile<128>(su + ABYTES, pb, 0, tid);
    CP_COMMIT();
    issue_tile<64>(su + BUFB, pa, BK, tid);
    issue_tile<128>(su + BUFB + ABYTES, pb, BK, tid);
    CP_COMMIT();

    int buf = 0, nxt = 2;
#pragma unroll 1
    for (int s = 0; s < NS; s++) {
        if (s + 1 < NS) CP_WAIT1(); else CP_WAIT0();
        __syncthreads();
        if (s + 2 < NS) {
            uint32_t nb = su + nxt * BUFB;
            issue_tile<64>(nb, pa, (s + 2) * BK, tid);
            issue_tile<128>(nb + ABYTES, pb, (s + 2) * BK, tid);
            CP_COMMIT();
            nxt = (nxt == 2) ? 0 : nxt + 1;
        }
        mma_stage(su + buf * BUFB, su + buf * BUFB + ABYTES, wm, wn, lane, acc);
        buf = (buf == 2) ? 0 : buf + 1;
    }
}

#define EPI_VARS()                               \
    const int tid = threadIdx.x;                 \
    const int w = tid >> 5, lane = tid & 31;     \
    const int g = lane >> 2, t = lane & 3;       \
    const int wm = (w & 1) * 32, wn = (w >> 1) * 32;

// ---------------------------------------------------------------------------
// Merged prep: grid (64, 8, 5), block (32, 8).
//   z=0..2 : Wq/Wk/Wv [k=256][c=f*8+h] -> Wt [n=h*256+f][k]  (smem transpose)
//   z=3    : X fp32 -> fp16 (vectorized)
//   z=4    : Wo [row=f*8+h][n] -> Wot [n][kk=h*256+f]
// ---------------------------------------------------------------------------
__global__ void prep_all(const float* __restrict__ X,
                         const float* __restrict__ Wq,
                         const float* __restrict__ Wk,
                         const float* __restrict__ Wv,
                         const float* __restrict__ Wo) {
    const int z = blockIdx.z;
    const int tx = threadIdx.x, ty = threadIdx.y;
    if (z < 3) {
        __shared__ float T[32][33];
        const float* src = (z == 0) ? Wq : (z == 1) ? Wk : Wv;
        __half* dst = (z == 0) ? g_Wqt : (z == 1) ? g_Wkt : g_Wvt;
        const int c0 = blockIdx.x * 32, k0 = blockIdx.y * 32;
#pragma unroll
        for (int i = 0; i < 4; i++)
            T[ty + 8 * i][tx] = src[(size_t)(k0 + ty + 8 * i) * FH + c0 + tx];
        __syncthreads();
#pragma unroll
        for (int i = 0; i < 4; i++) {
            int c = c0 + ty + 8 * i;
            int n = (c & 7) * 256 + (c >> 3);
            dst[(size_t)n * F_ + k0 + tx] = __float2half_rn(T[tx][ty + 8 * i]);
        }
    } else if (z == 3) {
        // 512 blocks x 256 threads x 8 floats = 1048576 = ROWS*F_
        const int blk = blockIdx.y * 64 + blockIdx.x;
        const int i = blk * 2048 + (ty * 32 + tx) * 8;
        float4 a = *(const float4*)(X + i);
        float4 b = *(const float4*)(X + i + 4);
        __half2 o[4];
        o[0] = __floats2half2_rn(a.x, a.y);
        o[1] = __floats2half2_rn(a.z, a.w);
        o[2] = __floats2half2_rn(b.x, b.y);
        o[3] = __floats2half2_rn(b.z, b.w);
        *(uint4*)&g_X[i] = *(const uint4*)o;
    } else {
        // 512 blocks x 256 threads x 4 floats = 524288 = FH*F_
        const int blk = blockIdx.y * 64 + blockIdx.x;
        const int i = blk * 1024 + (ty * 32 + tx) * 4;
        const int row = i >> 8, nn = i & 255;
        const int kk = ((row & 7) << 8) | (row >> 3);
        float4 wv = *(const float4*)(Wo + i);
        g_Wot[(size_t)(nn + 0) * FH + kk] = __float2half_rn(wv.x);
        g_Wot[(size_t)(nn + 1) * FH + kk] = __float2half_rn(wv.y);
        g_Wot[(size_t)(nn + 2) * FH + kk] = __float2half_rn(wv.z);
        g_Wot[(size_t)(nn + 3) * FH + kk] = __float2half_rn(wv.w);
    }
}

// ---------------------------------------------------------------------------
// QKV: C[4096, 2048], A=g_X, B=Wt.  grid (16 n, 64 m, 3 z)
// z=0/1 -> Q/K in [b,h][s][f];  z=2 -> V transposed into g_Vt [b,h][f][s]
// ---------------------------------------------------------------------------
__global__ __launch_bounds__(256, 3)
void qkv_kernel() {
    extern __shared__ char sm[];
    const int m0 = blockIdx.y * 64;
    const int n0 = blockIdx.x * 128;
    const int z = blockIdx.z;
    const __half* Wt = (z == 0) ? g_Wqt : (z == 1) ? g_Wkt : g_Wvt;
    const int h = n0 >> 8, f0 = n0 & 255;

    float acc[2][4][4];
    run_gemm<F_ / BK>(sm,
        [&](int r, int k) { return g_X + (size_t)(m0 + r) * F_ + k; },
        [&](int r, int k) { return Wt + (size_t)(n0 + r) * F_ + k; },
        acc);

    EPI_VARS();
    if (z != 2) {
        __half* dst = (z == 0) ? g_Q : g_K;
#pragma unroll
        for (int mt = 0; mt < 2; mt++) {
            int r0 = m0 + wm + 16 * mt + g;
            __half* b0 = dst + (size_t)((r0 >> 10) * H_ + h) * SF + (r0 & 1023) * F_;
            __half* b1 = b0 + 8 * F_;
#pragma unroll
            for (int nt = 0; nt < 4; nt++) {
                int col = f0 + wn + nt * 8 + 2 * t;
                *(__half2*)(b0 + col) = __floats2half2_rn(acc[mt][nt][0], acc[mt][nt][1]);
                *(__half2*)(b1 + col) = __floats2half2_rn(acc[mt][nt][2], acc[mt][nt][3]);
            }
        }
    } else {
        // stage transposed tile: tile[f_col (128)][s_row (64), pad to 72]
        __syncthreads();
        __half* tile = (__half*)sm;
#pragma unroll
        for (int mt = 0; mt < 2; mt++) {
            int lr = wm + 16 * mt + g;
#pragma unroll
            for (int nt = 0; nt < 4; nt++) {
                int cl = wn + 8 * nt + 2 * t;
                tile[(size_t)cl * 72 + lr]           = __float2half_rn(acc[mt][nt][0]);
                tile[(size_t)(cl + 1) * 72 + lr]     = __float2half_rn(acc[mt][nt][1]);
                tile[(size_t)cl * 72 + lr + 8]       = __float2half_rn(acc[mt][nt][2]);
                tile[(size_t)(cl + 1) * 72 + lr + 8] = __float2half_rn(acc[mt][nt][3]);
            }
        }
        __syncthreads();
        // drain: 128 f-rows x 8 chunks of 8 halves = 128 x 64 tile
        __half* base = g_Vt + (size_t)((m0 >> 10) * H_ + h) * SF + (m0 & 1023);
#pragma unroll
        for (int it = 0; it < 4; it++) {
            int idx = tid + it * 256;           // 0..1023
            int fr = idx >> 3, ch = idx & 7;
            uint4 v = *(const uint4*)&tile[(size_t)fr * 72 + ch * 8];
            *(uint4*)&base[(size_t)(f0 + fr) * S_ + ch * 8] = v;
        }
    }
}

// ---------------------------------------------------------------------------
// Scores: per z, S = sigmoid(16 * Q K^T).  grid (8 n, 16 m, 32 z)
// ---------------------------------------------------------------------------
__global__ __launch_bounds__(256, 3)
void scores_kernel() {
    extern __shared__ char sm[];
    const int m0 = blockIdx.y * 64;
    const int n0 = blockIdx.x * 128;
    const int z = blockIdx.z;
    const __half* Q = g_Q + (size_t)z * SF;
    const __half* Kp = g_K + (size_t)z * SF;
    __half* Sout = g_S + (size_t)z * SS;

    float acc[2][4][4];
    run_gemm<F_ / BK>(sm,
        [&](int r, int k) { return Q + (size_t)(m0 + r) * F_ + k; },
        [&](int r, int k) { return Kp + (size_t)(n0 + r) * F_ + k; },
        acc);

    EPI_VARS();
#pragma unroll
    for (int mt = 0; mt < 2; mt++) {
        int r0 = m0 + wm + 16 * mt + g;
#pragma unroll
        for (int nt = 0; nt < 4; nt++) {
            int col = n0 + wn + nt * 8 + 2 * t;
            *(__half2*)(Sout + (size_t)r0 * S_ + col) =
                __floats2half2_rn(sigm16(acc[mt][nt][0]), sigm16(acc[mt][nt][1]));
            *(__half2*)(Sout + (size_t)(r0 + 8) * S_ + col) =
                __floats2half2_rn(sigm16(acc[mt][nt][2]), sigm16(acc[mt][nt][3]));
        }
    }
}

// ---------------------------------------------------------------------------
// AV: per z, O = S @ V (B = Vt[f][s]).  grid (2 n, 16 m, 32 z)
// ---------------------------------------------------------------------------
__global__ __launch_bounds__(256, 3)
void av_kernel() {
    extern __shared__ char sm[];
    const int m0 = blockIdx.y * 64;
    const int n0 = blockIdx.x * 128;
    const int z = blockIdx.z;
    const __half* Sm = g_S + (size_t)z * SS;
    const __half* Vt = g_Vt + (size_t)z * SF;
    __half* O = g_O + (size_t)z * SF;

    float acc[2][4][4];
    run_gemm<S_ / BK>(sm,
        [&](int r, int k) { return Sm + (size_t)(m0 + r) * S_ + k; },
        [&](int r, int k) { return Vt + (size_t)(n0 + r) * S_ + k; },
        acc);

    EPI_VARS();
#pragma unroll
    for (int mt = 0; mt < 2; mt++) {
        int r0 = m0 + wm + 16 * mt + g;
#pragma unroll
        for (int nt = 0; nt < 4; nt++) {
            int col = n0 + wn + nt * 8 + 2 * t;
            *(__half2*)(O + (size_t)r0 * F_ + col) =
                __floats2half2_rn(acc[mt][nt][0], acc[mt][nt][1]);
            *(__half2*)(O + (size_t)(r0 + 8) * F_ + col) =
                __floats2half2_rn(acc[mt][nt][2], acc[mt][nt][3]);
        }
    }
}

// ---------------------------------------------------------------------------
// OUT split-K=4: P[split] = O'(k-chunk) @ Wot.  grid (2 n, 64 m, 4 split)
// ---------------------------------------------------------------------------
__global__ __launch_bounds__(256, 3)
void out_kernel() {
    extern __shared__ char sm[];
    const int m0 = blockIdx.y * 64;
    const int n0 = blockIdx.x * 128;
    const int kbase = blockIdx.z * (FH / KSPLIT);
    float* P = g_P[blockIdx.z];

    float acc[2][4][4];
    run_gemm<(FH / KSPLIT) / BK>(sm,
        [&](int r, int k) {
            int kk = kbase + k;
            int h = kk >> 8, f = kk & 255;
            int rg = m0 + r;
            return g_O + (size_t)((rg >> 10) * H_ + h) * SF + (rg & 1023) * F_ + f;
        },
        [&](int r, int k) { return g_Wot + (size_t)(n0 + r) * FH + kbase + k; },
        acc);

    EPI_VARS();
#pragma unroll
    for (int mt = 0; mt < 2; mt++) {
        int r0 = m0 + wm + 16 * mt + g;
#pragma unroll
        for (int nt = 0; nt < 4; nt++) {
            int col = n0 + wn + nt * 8 + 2 * t;
            *(float2*)(P + (size_t)r0 * F_ + col) =
                make_float2(acc[mt][nt][0], acc[mt][nt][1]);
            *(float2*)(P + (size_t)(r0 + 8) * F_ + col) =
                make_float2(acc[mt][nt][2], acc[mt][nt][3]);
        }
    }
}

__global__ void reduce_relu_kernel(float* __restrict__ out) {
    const int i = (blockIdx.x * 256 + threadIdx.x) * 4;
    float4 s = *(const float4*)&g_P[0][i];
#pragma unroll
    for (int p = 1; p < KSPLIT; p++) {
        float4 v = *(const float4*)&g_P[p][i];
        s.x += v.x; s.y += v.y; s.z += v.z; s.w += v.w;
    }
    s.x = fmaxf(s.x, 0.f); s.y = fmaxf(s.y, 0.f);
    s.z = fmaxf(s.z, 0.f); s.w = fmaxf(s.w, 0.f);
    *(float4*)&out[i] = s;
}

// ---------------------------------------------------------------------------
extern "C" void kernel_launch(void* const* d_in, const int* in_sizes, int n_in,
                              void* d_out, int out_size) {
    const float* q_input = (const float*)d_in[0];
    const float* Wq = (const float*)d_in[1];
    const float* Wk = (const float*)d_in[2];
    const float* Wv = (const float*)d_in[3];
    const float* Wo = (const float*)d_in[4];
    float* out = (float*)d_out;

    cudaFuncSetAttribute(qkv_kernel, cudaFuncAttributeMaxDynamicSharedMemorySize, SMEM_ALL);
    cudaFuncSetAttribute(scores_kernel, cudaFuncAttributeMaxDynamicSharedMemorySize, SMEM_ALL);
    cudaFuncSetAttribute(av_kernel, cudaFuncAttributeMaxDynamicSharedMemorySize, SMEM_ALL);
    cudaFuncSetAttribute(out_kernel, cudaFuncAttributeMaxDynamicSharedMemorySize, SMEM_ALL);

    { dim3 g(64, 8, 5), b(32, 8); prep_all<<<g, b>>>(q_input, Wq, Wk, Wv, Wo); }

    { dim3 g(16, 64, 3); qkv_kernel<<<g, 256, SMEM_ALL>>>(); }
    { dim3 g(8, 16, 32); scores_kernel<<<g, 256, SMEM_ALL>>>(); }
    { dim3 g(2, 16, 32); av_kernel<<<g, 256, SMEM_ALL>>>(); }
    { dim3 g(2, 64, KSPLIT); out_kernel<<<g, 256, SMEM_ALL>>>(); }
    reduce_relu_kernel<<<ROWS * F_ / 1024, 256>>>(out);
}

// round 17
// speedup vs baseline: 6.9125x; 1.0028x over previous
#include <cuda_runtime.h>
#include <cuda_fp16.h>
#include <cstdint>
#include <math.h>

// ---------------------------------------------------------------------------
// Problem constants
// ---------------------------------------------------------------------------
#define B_   4
#define S_   1024
#define F_   256
#define H_   8
#define ROWS 4096
#define FH   2048
#define BH   32
#define SF   262144            // S_*F_ per (b,h)
#define SS   1048576           // S_*S_ per (b,h)

#define BK   64                // k elems per smem stage (128 bytes fp16)
// All GEMMs: TM=64 (MT=2), TN=128. Buffer = (64+128)*128B = 24576.
#define SMEM_ALL  73728        // 3 buffers
#define KSPLIT 4

// ---------------------------------------------------------------------------
// Scratch (__device__ globals; allocation-free)
// ---------------------------------------------------------------------------
__device__ __half g_X[ROWS * F_];
__device__ __half g_Wqt[FH * F_];       // [n=h*256+f][k]
__device__ __half g_Wkt[FH * F_];
__device__ __half g_Wvt[FH * F_];
__device__ __half g_Wot[F_ * FH];       // [n][kk=h*256+f]
__device__ __half g_Q[BH * SF];         // [b,h][s][f]
__device__ __half g_K[BH * SF];
__device__ __half g_Vt[BH * SF];        // [b,h][f][s]
__device__ __half g_O[BH * SF];
__device__ __half g_S[(size_t)BH * SS]; // [b,h][i][j]
__device__ float  g_P[KSPLIT][ROWS * F_]; // split-K partials

// ---------------------------------------------------------------------------
// PTX helpers
// ---------------------------------------------------------------------------
__device__ __forceinline__ uint32_t smem_u32(const void* p) {
    uint32_t a;
    asm("{ .reg .u64 t; cvta.to.shared.u64 t, %1; cvt.u32.u64 %0, t; }"
        : "=r"(a) : "l"(p));
    return a;
}

__device__ __forceinline__ void cp16(uint32_t dst, const void* src) {
    asm volatile("cp.async.cg.shared.global [%0], [%1], 16;\n"
                 :: "r"(dst), "l"(src));
}
#define CP_COMMIT() asm volatile("cp.async.commit_group;\n" ::: "memory")
#define CP_WAIT0()  asm volatile("cp.async.wait_group 0;\n" ::: "memory")
#define CP_WAIT1()  asm volatile("cp.async.wait_group 1;\n" ::: "memory")

__device__ __forceinline__ void mma16816(float d[4], const uint32_t a[4],
                                         const uint32_t b[2]) {
    asm volatile(
        "mma.sync.aligned.m16n8k16.row.col.f32.f16.f16.f32 "
        "{%0,%1,%2,%3},{%4,%5,%6,%7},{%8,%9},{%0,%1,%2,%3};\n"
        : "+f"(d[0]), "+f"(d[1]), "+f"(d[2]), "+f"(d[3])
        : "r"(a[0]), "r"(a[1]), "r"(a[2]), "r"(a[3]), "r"(b[0]), "r"(b[1]));
}

#define LDSM4(r0, r1, r2, r3, addr) \
    asm volatile("ldmatrix.sync.aligned.m8n8.x4.shared.b16 {%0,%1,%2,%3}, [%4];" \
                 : "=r"(r0), "=r"(r1), "=r"(r2), "=r"(r3) : "r"(addr))

// sigmoid(16x) = 0.5 + 0.5*tanh(8x)  (tanh.approx: 1 MUFU)
__device__ __forceinline__ float sigm16(float x) {
    float t;
    asm("tanh.approx.f32 %0, %1;" : "=f"(t) : "f"(8.0f * x));
    return 0.5f + 0.5f * t;
}

// ---------------------------------------------------------------------------
// Tile fill: NR rows x 64 fp16 (128B rows), chunk swizzle c ^ (row&7).
// ---------------------------------------------------------------------------
template <int NR, class P>
__device__ __forceinline__ void issue_tile(uint32_t sbase, P p, int k0, int tid) {
#pragma unroll
    for (int it = 0; it < NR * 8 / 256; it++) {
        int idx = tid + it * 256;
        int row = idx >> 3, c = idx & 7;
        uint32_t dst = sbase + row * 128 + ((c ^ (row & 7)) << 4);
        cp16(dst, p(row, k0 + c * 8));
    }
}

// ---------------------------------------------------------------------------
// One BK=64 stage: warp tile 32 x 32, ldmatrix.x4 fragments.
// ---------------------------------------------------------------------------
__device__ __forceinline__ void mma_stage(uint32_t Abase, uint32_t Bbase,
                                          int wm, int wn, int lane,
                                          float acc[2][4][4]) {
    const int l15 = lane & 15;
    const int l7 = lane & 7;
    const int hiA = lane >> 4;
    const int bm = lane >> 3;
    const int ntoff = (bm >> 1) << 3;
    const int chp = bm & 1;
#pragma unroll
    for (int kk = 0; kk < BK; kk += 16) {
        const int ch = kk >> 3;
        uint32_t a[2][4], b[4][2];
#pragma unroll
        for (int mt = 0; mt < 2; mt++) {
            int row = wm + 16 * mt + l15;
            uint32_t addr = Abase + row * 128 + ((uint32_t)((ch + hiA) ^ l7) << 4);
            LDSM4(a[mt][0], a[mt][1], a[mt][2], a[mt][3], addr);
        }
#pragma unroll
        for (int half = 0; half < 2; half++) {
            int row = wn + half * 16 + ntoff + l7;
            uint32_t addr = Bbase + row * 128 + ((uint32_t)((ch + chp) ^ l7) << 4);
            LDSM4(b[2 * half][0], b[2 * half][1],
                  b[2 * half + 1][0], b[2 * half + 1][1], addr);
        }
#pragma unroll
        for (int mt = 0; mt < 2; mt++)
#pragma unroll
            for (int nt = 0; nt < 4; nt++)
                mma16816(acc[mt][nt], a[mt], b[nt]);
    }
}

// ---------------------------------------------------------------------------
// Mainloop: TILES consecutive tiles of NS stages each, one rolling 3-deep
// cp.async ring across tile boundaries. pa/pb take (tile, row, kElem).
// epi(tile, acc) fires after each tile's last stage (GMEM-only stores for
// TILES>1; smem-using epilogues only allowed when TILES==1, where all copies
// have drained).
// ---------------------------------------------------------------------------
template <int NS, int TILES, class PA, class PB, class EPI>
__device__ __forceinline__ void run_gemm(char* sm, PA pa, PB pb, EPI epi) {
    const int tid = threadIdx.x;
    const int w = tid >> 5, lane = tid & 31;
    const int wm = (w & 1) * 32, wn = (w >> 1) * 32;
    const uint32_t su = smem_u32(sm);
    constexpr uint32_t ABYTES = 64 * 128;
    constexpr uint32_t BUFB = ABYTES + 16384;   // 24576
    constexpr int TOT = NS * TILES;

    float acc[2][4][4];
#pragma unroll
    for (int i = 0; i < 2; i++)
#pragma unroll
        for (int j = 0; j < 4; j++)
#pragma unroll
            for (int q = 0; q < 4; q++) acc[i][j][q] = 0.f;

    auto issue = [&](int st, uint32_t base) {
        const int tt = st / NS, k0 = (st % NS) * BK;
        issue_tile<64>(base, [&](int r, int k) { return pa(tt, r, k); }, k0, tid);
        issue_tile<128>(base + ABYTES, [&](int r, int k) { return pb(tt, r, k); }, k0, tid);
        CP_COMMIT();
    };

    issue(0, su);
    issue(1, su + BUFB);

    int buf = 0, nxt = 2;
#pragma unroll 1
    for (int st = 0; st < TOT; st++) {
        if (st + 1 < TOT) CP_WAIT1(); else CP_WAIT0();
        __syncthreads();
        if (st + 2 < TOT) {
            issue(st + 2, su + nxt * BUFB);
            nxt = (nxt == 2) ? 0 : nxt + 1;
        }
        mma_stage(su + buf * BUFB, su + buf * BUFB + ABYTES, wm, wn, lane, acc);
        buf = (buf == 2) ? 0 : buf + 1;
        if ((st + 1) % NS == 0) {
            epi(st / NS, acc);
#pragma unroll
            for (int i = 0; i < 2; i++)
#pragma unroll
                for (int j = 0; j < 4; j++)
#pragma unroll
                    for (int q = 0; q < 4; q++) acc[i][j][q] = 0.f;
        }
    }
}

#define EPI_VARS()                               \
    const int tid = threadIdx.x;                 \
    const int w = tid >> 5, lane = tid & 31;     \
    const int g = lane >> 2, t = lane & 3;       \
    const int wm = (w & 1) * 32, wn = (w >> 1) * 32;

// ---------------------------------------------------------------------------
// Merged prep: grid (64, 8, 5), block (32, 8).
//   z=0..2 : Wq/Wk/Wv [k=256][c=f*8+h] -> Wt [n=h*256+f][k]  (smem transpose)
//   z=3    : X fp32 -> fp16 (vectorized)
//   z=4    : Wo [row=f*8+h][n] -> Wot [n][kk=h*256+f]
// ---------------------------------------------------------------------------
__global__ void prep_all(const float* __restrict__ X,
                         const float* __restrict__ Wq,
                         const float* __restrict__ Wk,
                         const float* __restrict__ Wv,
                         const float* __restrict__ Wo) {
    const int z = blockIdx.z;
    const int tx = threadIdx.x, ty = threadIdx.y;
    if (z < 3) {
        __shared__ float T[32][33];
        const float* src = (z == 0) ? Wq : (z == 1) ? Wk : Wv;
        __half* dst = (z == 0) ? g_Wqt : (z == 1) ? g_Wkt : g_Wvt;
        const int c0 = blockIdx.x * 32, k0 = blockIdx.y * 32;
#pragma unroll
        for (int i = 0; i < 4; i++)
            T[ty + 8 * i][tx] = src[(size_t)(k0 + ty + 8 * i) * FH + c0 + tx];
        __syncthreads();
#pragma unroll
        for (int i = 0; i < 4; i++) {
            int c = c0 + ty + 8 * i;
            int n = (c & 7) * 256 + (c >> 3);
            dst[(size_t)n * F_ + k0 + tx] = __float2half_rn(T[tx][ty + 8 * i]);
        }
    } else if (z == 3) {
        const int blk = blockIdx.y * 64 + blockIdx.x;
        const int i = blk * 2048 + (ty * 32 + tx) * 8;
        float4 a = *(const float4*)(X + i);
        float4 b = *(const float4*)(X + i + 4);
        __half2 o[4];
        o[0] = __floats2half2_rn(a.x, a.y);
        o[1] = __floats2half2_rn(a.z, a.w);
        o[2] = __floats2half2_rn(b.x, b.y);
        o[3] = __floats2half2_rn(b.z, b.w);
        *(uint4*)&g_X[i] = *(const uint4*)o;
    } else {
        const int blk = blockIdx.y * 64 + blockIdx.x;
        const int i = blk * 1024 + (ty * 32 + tx) * 4;
        const int row = i >> 8, nn = i & 255;
        const int kk = ((row & 7) << 8) | (row >> 3);
        float4 wv = *(const float4*)(Wo + i);
        g_Wot[(size_t)(nn + 0) * FH + kk] = __float2half_rn(wv.x);
        g_Wot[(size_t)(nn + 1) * FH + kk] = __float2half_rn(wv.y);
        g_Wot[(size_t)(nn + 2) * FH + kk] = __float2half_rn(wv.z);
        g_Wot[(size_t)(nn + 3) * FH + kk] = __float2half_rn(wv.w);
    }
}

// ---------------------------------------------------------------------------
// QKV: C[4096, 2048], A=g_X, B=Wt.  grid (16 n, 64 m, 3 z), TILES=1
// z=0/1 -> Q/K in [b,h][s][f];  z=2 -> V transposed into g_Vt [b,h][f][s]
// ---------------------------------------------------------------------------
__global__ __launch_bounds__(256, 3)
void qkv_kernel() {
    extern __shared__ char sm[];
    const int m0 = blockIdx.y * 64;
    const int n0 = blockIdx.x * 128;
    const int z = blockIdx.z;
    const __half* Wt = (z == 0) ? g_Wqt : (z == 1) ? g_Wkt : g_Wvt;
    const int h = n0 >> 8, f0 = n0 & 255;

    EPI_VARS();
    run_gemm<F_ / BK, 1>(sm,
        [&](int tt, int r, int k) { return g_X + (size_t)(m0 + r) * F_ + k; },
        [&](int tt, int r, int k) { return Wt + (size_t)(n0 + r) * F_ + k; },
        [&](int tt, float (&acc)[2][4][4]) {
            if (z != 2) {
                __half* dst = (z == 0) ? g_Q : g_K;
#pragma unroll
                for (int mt = 0; mt < 2; mt++) {
                    int r0 = m0 + wm + 16 * mt + g;
                    __half* b0 = dst + (size_t)((r0 >> 10) * H_ + h) * SF + (r0 & 1023) * F_;
                    __half* b1 = b0 + 8 * F_;
#pragma unroll
                    for (int nt = 0; nt < 4; nt++) {
                        int col = f0 + wn + nt * 8 + 2 * t;
                        *(__half2*)(b0 + col) = __floats2half2_rn(acc[mt][nt][0], acc[mt][nt][1]);
                        *(__half2*)(b1 + col) = __floats2half2_rn(acc[mt][nt][2], acc[mt][nt][3]);
                    }
                }
            } else {
                // stage transposed tile: tile[f_col (128)][s_row (64), pad to 72]
                // TILES==1: all cp.async drained; smem ring is dead here.
                __syncthreads();
                __half* tile = (__half*)sm;
#pragma unroll
                for (int mt = 0; mt < 2; mt++) {
                    int lr = wm + 16 * mt + g;
#pragma unroll
                    for (int nt = 0; nt < 4; nt++) {
                        int cl = wn + 8 * nt + 2 * t;
                        tile[(size_t)cl * 72 + lr]           = __float2half_rn(acc[mt][nt][0]);
                        tile[(size_t)(cl + 1) * 72 + lr]     = __float2half_rn(acc[mt][nt][1]);
                        tile[(size_t)cl * 72 + lr + 8]       = __float2half_rn(acc[mt][nt][2]);
                        tile[(size_t)(cl + 1) * 72 + lr + 8] = __float2half_rn(acc[mt][nt][3]);
                    }
                }
                __syncthreads();
                __half* base = g_Vt + (size_t)((m0 >> 10) * H_ + h) * SF + (m0 & 1023);
#pragma unroll
                for (int it = 0; it < 4; it++) {
                    int idx = tid + it * 256;           // 0..1023
                    int fr = idx >> 3, ch = idx & 7;
                    uint4 v = *(const uint4*)&tile[(size_t)fr * 72 + ch * 8];
                    *(uint4*)&base[(size_t)(f0 + fr) * S_ + ch * 8] = v;
                }
            }
        });
}

// ---------------------------------------------------------------------------
// Scores: per z, S = sigmoid(16 * Q K^T).  grid (8 n, 4 m, 32 z), TILES=4:
// each CTA chains 4 m-tiles (m_base + tt*64) over the same n0 — pipeline fill
// amortized over 16 stages instead of 4.
// ---------------------------------------------------------------------------
__global__ __launch_bounds__(256, 3)
void scores_kernel() {
    extern __shared__ char sm[];
    const int m_base = blockIdx.y * 256;
    const int n0 = blockIdx.x * 128;
    const int z = blockIdx.z;
    const __half* Q = g_Q + (size_t)z * SF;
    const __half* Kp = g_K + (size_t)z * SF;
    __half* Sout = g_S + (size_t)z * SS;

    EPI_VARS();
    run_gemm<F_ / BK, 4>(sm,
        [&](int tt, int r, int k) { return Q + (size_t)(m_base + tt * 64 + r) * F_ + k; },
        [&](int tt, int r, int k) { return Kp + (size_t)(n0 + r) * F_ + k; },
        [&](int tt, float (&acc)[2][4][4]) {
            const int m0 = m_base + tt * 64;
#pragma unroll
            for (int mt = 0; mt < 2; mt++) {
                int r0 = m0 + wm + 16 * mt + g;
#pragma unroll
                for (int nt = 0; nt < 4; nt++) {
                    int col = n0 + wn + nt * 8 + 2 * t;
                    *(__half2*)(Sout + (size_t)r0 * S_ + col) =
                        __floats2half2_rn(sigm16(acc[mt][nt][0]), sigm16(acc[mt][nt][1]));
                    *(__half2*)(Sout + (size_t)(r0 + 8) * S_ + col) =
                        __floats2half2_rn(sigm16(acc[mt][nt][2]), sigm16(acc[mt][nt][3]));
                }
            }
        });
}

// ---------------------------------------------------------------------------
// AV: per z, O = S @ V (B = Vt[f][s]).  grid (2 n, 16 m, 32 z), TILES=1
// ---------------------------------------------------------------------------
__global__ __launch_bounds__(256, 3)
void av_kernel() {
    extern __shared__ char sm[];
    const int m0 = blockIdx.y * 64;
    const int n0 = blockIdx.x * 128;
    const int z = blockIdx.z;
    const __half* Sm = g_S + (size_t)z * SS;
    const __half* Vt = g_Vt + (size_t)z * SF;
    __half* O = g_O + (size_t)z * SF;

    EPI_VARS();
    run_gemm<S_ / BK, 1>(sm,
        [&](int tt, int r, int k) { return Sm + (size_t)(m0 + r) * S_ + k; },
        [&](int tt, int r, int k) { return Vt + (size_t)(n0 + r) * S_ + k; },
        [&](int tt, float (&acc)[2][4][4]) {
#pragma unroll
            for (int mt = 0; mt < 2; mt++) {
                int r0 = m0 + wm + 16 * mt + g;
#pragma unroll
                for (int nt = 0; nt < 4; nt++) {
                    int col = n0 + wn + nt * 8 + 2 * t;
                    *(__half2*)(O + (size_t)r0 * F_ + col) =
                        __floats2half2_rn(acc[mt][nt][0], acc[mt][nt][1]);
                    *(__half2*)(O + (size_t)(r0 + 8) * F_ + col) =
                        __floats2half2_rn(acc[mt][nt][2], acc[mt][nt][3]);
                }
            }
        });
}

// ---------------------------------------------------------------------------
// OUT split-K=4: P[split] = O'(k-chunk) @ Wot.  grid (2 n, 64 m, 4 split)
// ---------------------------------------------------------------------------
__global__ __launch_bounds__(256, 3)
void out_kernel() {
    extern __shared__ char sm[];
    const int m0 = blockIdx.y * 64;
    const int n0 = blockIdx.x * 128;
    const int kbase = blockIdx.z * (FH / KSPLIT);
    float* P = g_P[blockIdx.z];

    EPI_VARS();
    run_gemm<(FH / KSPLIT) / BK, 1>(sm,
        [&](int tt, int r, int k) {
            int kk = kbase + k;
            int h = kk >> 8, f = kk & 255;
            int rg = m0 + r;
            return g_O + (size_t)((rg >> 10) * H_ + h) * SF + (rg & 1023) * F_ + f;
        },
        [&](int tt, int r, int k) { return g_Wot + (size_t)(n0 + r) * FH + kbase + k; },
        [&](int tt, float (&acc)[2][4][4]) {
#pragma unroll
            for (int mt = 0; mt < 2; mt++) {
                int r0 = m0 + wm + 16 * mt + g;
#pragma unroll
                for (int nt = 0; nt < 4; nt++) {
                    int col = n0 + wn + nt * 8 + 2 * t;
                    *(float2*)(P + (size_t)r0 * F_ + col) =
                        make_float2(acc[mt][nt][0], acc[mt][nt][1]);
                    *(float2*)(P + (size_t)(r0 + 8) * F_ + col) =
                        make_float2(acc[mt][nt][2], acc[mt][nt][3]);
                }
            }
        });
}

__global__ void reduce_relu_kernel(float* __restrict__ out) {
    const int i = (blockIdx.x * 256 + threadIdx.x) * 4;
    float4 s = *(const float4*)&g_P[0][i];
#pragma unroll
    for (int p = 1; p < KSPLIT; p++) {
        float4 v = *(const float4*)&g_P[p][i];
        s.x += v.x; s.y += v.y; s.z += v.z; s.w += v.w;
    }
    s.x = fmaxf(s.x, 0.f); s.y = fmaxf(s.y, 0.f);
    s.z = fmaxf(s.z, 0.f); s.w = fmaxf(s.w, 0.f);
    *(float4*)&out[i] = s;
}

// ---------------------------------------------------------------------------
extern "C" void kernel_launch(void* const* d_in, const int* in_sizes, int n_in,
                              void* d_out, int out_size) {
    const float* q_input = (const float*)d_in[0];
    const float* Wq = (const float*)d_in[1];
    const float* Wk = (const float*)d_in[2];
    const float* Wv = (const float*)d_in[3];
    const float* Wo = (const float*)d_in[4];
    float* out = (float*)d_out;

    cudaFuncSetAttribute(qkv_kernel, cudaFuncAttributeMaxDynamicSharedMemorySize, SMEM_ALL);
    cudaFuncSetAttribute(scores_kernel, cudaFuncAttributeMaxDynamicSharedMemorySize, SMEM_ALL);
    cudaFuncSetAttribute(av_kernel, cudaFuncAttributeMaxDynamicSharedMemorySize, SMEM_ALL);
    cudaFuncSetAttribute(out_kernel, cudaFuncAttributeMaxDynamicSharedMemorySize, SMEM_ALL);

    { dim3 g(64, 8, 5), b(32, 8); prep_all<<<g, b>>>(q_input, Wq, Wk, Wv, Wo); }

    { dim3 g(16, 64, 3); qkv_kernel<<<g, 256, SMEM_ALL>>>(); }
    { dim3 g(8, 4, 32); scores_kernel<<<g, 256, SMEM_ALL>>>(); }
    { dim3 g(2, 16, 32); av_kernel<<<g, 256, SMEM_ALL>>>(); }
    { dim3 g(2, 64, KSPLIT); out_kernel<<<g, 256, SMEM_ALL>>>(); }
    reduce_relu_kernel<<<ROWS * F_ / 1024, 256>>>(out);
}